// round 4
// baseline (speedup 1.0000x reference)
#include <cuda_runtime.h>
#include <cuda_bf16.h>
#include <cstdint>

// Scratch in static device memory. Layouts: [location][channel/k][batch], batch innermost.
__device__ float g_P0[400 * 54 * 4096];      // im2col of x
__device__ float g_H0[400 * 32 * 4096];      // layer0 out
__device__ float g_H1[100 * 64 * 4096];      // layer1 out
__device__ float g_H2[4 * 128 * 4096];       // layer2 out
__device__ float g_PART[8 * 4 * 128 * 4096]; // layer2 split-K partials [kz][loc][co][b]

static __device__ __forceinline__ float tanhap(float x) {
    float y; asm("tanh.approx.f32 %0, %1;" : "=f"(y) : "f"(x)); return y;
}
static __device__ __forceinline__ unsigned long long pack2(float w) {
    unsigned long long p; asm("mov.b64 %0, {%1, %1};" : "=l"(p) : "f"(w)); return p;
}
static __device__ __forceinline__ void ffma2(unsigned long long& acc,
                                             unsigned long long a, unsigned long long w2) {
    asm("fma.rn.f32x2 %0, %1, %2, %0;" : "+l"(acc) : "l"(a), "l"(w2));
}
static __device__ __forceinline__ void cpa16(void* s, const void* g) {
    uint32_t sa = (uint32_t)__cvta_generic_to_shared(s);
    asm volatile("cp.async.ca.shared.global [%0], [%1], 16;" :: "r"(sa), "l"(g));
}
static __device__ __forceinline__ void cpa_wait() {
    asm volatile("cp.async.commit_group;");
    asm volatile("cp.async.wait_group 0;");
}

// ---------------------------------------------------------------------------
// im2col: x[B,6,60,60] -> g_P0[loc][k][B]
// ---------------------------------------------------------------------------
__global__ void __launch_bounds__(256) im2col_k(const float* __restrict__ x) {
    const int ch = blockIdx.x;          // 0..359
    const int c = ch / 60, h = ch % 60;
    const int b0 = blockIdx.y * 32;
    __shared__ float s[32 * 61];
    const float* src = x + ((size_t)b0 * 6 + c) * 3600 + (size_t)h * 60;
    for (int e = threadIdx.x; e < 32 * 60; e += 256) {
        int bl = e / 60, w = e - bl * 60;
        s[bl * 61 + w] = src[(size_t)bl * 21600 + w];
    }
    __syncthreads();
    const int i = h / 3, dh = h % 3;
    for (int e = threadIdx.x; e < 32 * 60; e += 256) {
        int w = e >> 5, bl = e & 31;
        int j = w / 3, dw = w - j * 3;
        g_P0[((size_t)(i * 20 + j) * 54 + c * 9 + dh * 3 + dw) * 4096 + b0 + bl] =
            s[bl * 61 + w];
    }
}

// ---------------------------------------------------------------------------
// Locally-connected GEMM. 256 threads. Tile: BB=256 batches x COUT_BLK=32 couts.
// Weights pre-duplicated in smem ({w,w} float2) -> single broadcast LDS.64.
// Thread: lane = batch-pair selector, cgrp (0..7) = cout group of NC=4.
// Register tile: NC=4 x NB2=4 = 16 u64 accumulators (32 regs).
// Dynamic smem: [ KCHUNK*BB floats A | COUT_BLK*KCHUNK float2 Wdup ].
// ---------------------------------------------------------------------------
template <int CIN, int KH, int KW, int WIN, int WOUT, int COUT,
          int KCHUNK, int KSPLIT, bool PARTIAL, int KZSTRIDE>
static __device__ __forceinline__ void lc_gemm_body(const float* __restrict__ in,
                                                    const float* __restrict__ W,
                                                    const float* __restrict__ bias,
                                                    float* __restrict__ out) {
    constexpr int COUT_BLK = 32;
    constexpr int BB   = 256;
    constexpr int K    = CIN * KH * KW;
    constexpr int KPER = K / KSPLIT;
    constexpr int NC   = 4;             // couts per thread
    constexpr int NB2  = 4;             // u64 batch-pairs per thread
    constexpr int B    = 4096;

    extern __shared__ __align__(16) float dsm[];
    float*  as  = dsm;                          // [KCHUNK][BB]
    float2* ws2 = (float2*)(dsm + KCHUNK * BB); // [COUT_BLK][KCHUNK] dup pairs

    const int loc = blockIdx.x;
    const int i = loc / WOUT, j = loc - i * WOUT;
    const int b0 = blockIdx.y * BB;
    const int cz = (blockIdx.z / KSPLIT) * COUT_BLK;
    const int kz = blockIdx.z % KSPLIT;
    const int t = threadIdx.x;
    const int lane = t & 31;
    const int cgrp = t >> 5;

    const float* Wl = W + ((size_t)loc * COUT + cz) * K;
    float* ob = out + (size_t)kz * KZSTRIDE;

    unsigned long long acc[NC][NB2];
#pragma unroll
    for (int c = 0; c < NC; c++) {
        unsigned long long p = PARTIAL ? 0ull
            : pack2(bias[(size_t)loc * COUT + cz + cgrp * NC + c]);
#pragma unroll
        for (int p2 = 0; p2 < NB2; p2++) acc[c][p2] = p;
    }

    const int kbeg = kz * KPER, kend = kbeg + KPER;
    for (int k0 = kbeg; k0 < kend; k0 += KCHUNK) {
        // A tile via cp.async (rows contiguous in `in`, 16B-aligned)
        for (int id = t; id < KCHUNK * BB / 4; id += 256) {
            int kc = id / (BB / 4), off = (id % (BB / 4)) * 4;
            int k = k0 + kc;
            int c = k / (KH * KW);
            int r = k - c * (KH * KW);
            int dh = r / KW, dw = r - dh * KW;
            int loc_in = (KH * i + dh) * WIN + KW * j + dw;
            cpa16(&as[kc * BB + off],
                  in + ((size_t)loc_in * CIN + c) * B + b0 + off);
        }
        // W tile, duplicated
        for (int id = t; id < COUT_BLK * KCHUNK; id += 256) {
            int co = id / KCHUNK, kc = id - co * KCHUNK;
            float w = __ldg(Wl + (size_t)co * K + k0 + kc);
            ws2[id] = make_float2(w, w);
        }
        cpa_wait();
        __syncthreads();

        const unsigned long long* a2  = (const unsigned long long*)as;
        const unsigned long long* w2p = (const unsigned long long*)ws2;
#pragma unroll 2
        for (int kc = 0; kc < KCHUNK; kc++) {
            unsigned long long a[NB2];
#pragma unroll
            for (int p = 0; p < NB2; p++) a[p] = a2[kc * (BB / 2) + p * 32 + lane];
#pragma unroll
            for (int c = 0; c < NC; c++) {
                unsigned long long w2 = w2p[(cgrp * NC + c) * KCHUNK + kc];
#pragma unroll
                for (int p = 0; p < NB2; p++) ffma2(acc[c][p], a[p], w2);
            }
        }
        __syncthreads();
    }

#pragma unroll
    for (int c = 0; c < NC; c++) {
        size_t obase = ((size_t)loc * COUT + cz + cgrp * NC + c) * B + b0;
#pragma unroll
        for (int p = 0; p < NB2; p++) {
            float x0, x1;
            asm("mov.b64 {%0, %1}, %2;" : "=f"(x0), "=f"(x1) : "l"(acc[c][p]));
            if (!PARTIAL) { x0 = tanhap(x0); x1 = tanhap(x1); }
            ((float2*)(ob + obase + p * 64))[lane] = make_float2(x0, x1);
        }
    }
}

// L0: K=54 over g_P0 (1x1 "kernel"), KCHUNK=27.
__global__ void __launch_bounds__(256, 3) k_l0(const float* __restrict__ W,
                                               const float* __restrict__ b) {
    lc_gemm_body<54, 1, 1, 20, 20, 32, 27, 1, false, 0>(g_P0, W, b, g_H0);
}
// L1: K=128, KCHUNK=32, cout-split 2.
__global__ void __launch_bounds__(256, 3) k_l1(const float* __restrict__ W,
                                               const float* __restrict__ b) {
    lc_gemm_body<32, 2, 2, 20, 10, 64, 32, 1, false, 0>(g_H0, W, b, g_H1);
}
// L2: K=1600, split-K=8 (KPER=200, KCHUNK=40), 4 cout blocks, partials.
__global__ void __launch_bounds__(256, 3) k_l2(const float* __restrict__ W,
                                               const float* __restrict__ b) {
    lc_gemm_body<64, 5, 5, 10, 2, 128, 40, 8, true, 4 * 128 * 4096>(g_H1, W, b, g_PART);
}

// Reduce 8 split-K partials + bias + tanh -> g_H2 (float4 per thread)
__global__ void __launch_bounds__(256) l2_combine_k(const float* __restrict__ B2) {
    constexpr int ST4 = 4 * 128 * 4096 / 4;
    int idx4 = blockIdx.x * 256 + threadIdx.x;
    int row = idx4 >> 10;                         // loc*128+co
    const float4* p = (const float4*)g_PART;
    float4 s = p[idx4];
#pragma unroll
    for (int z = 1; z < 8; z++) {
        float4 v = p[idx4 + z * ST4];
        s.x += v.x; s.y += v.y; s.z += v.z; s.w += v.w;
    }
    float bv = B2[row];
    ((float4*)g_H2)[idx4] = make_float4(tanhap(s.x + bv), tanhap(s.y + bv),
                                        tanhap(s.z + bv), tanhap(s.w + bv));
}

// ---------------------------------------------------------------------------
// Classifier + softmax. 128 blocks x 256 threads: 32 batches x 8 f-groups.
// ---------------------------------------------------------------------------
__global__ void __launch_bounds__(256) classifier_k(const float* __restrict__ info,
                                                    const float* __restrict__ Wc,
                                                    const float* __restrict__ bc,
                                                    float* __restrict__ out) {
    __shared__ float wsm[1030];
    __shared__ float red[8][32][2];
    for (int e = threadIdx.x; e < 1028; e += 256) wsm[e] = Wc[e];
    if (threadIdx.x < 2) wsm[1028 + threadIdx.x] = bc[threadIdx.x];
    __syncthreads();

    const int fg = threadIdx.x >> 5, lane = threadIdx.x & 31;
    const int b = blockIdx.x * 32 + lane;
    float l0 = 0.f, l1 = 0.f;
#pragma unroll 8
    for (int ff = 0; ff < 64; ff++) {
        int f = fg * 64 + ff;
        int row = (f & 3) * 128 + (f >> 2);
        float hv = g_H2[(size_t)row * 4096 + b];
        l0 += hv * wsm[f * 2];
        l1 += hv * wsm[f * 2 + 1];
    }
    red[fg][lane][0] = l0;
    red[fg][lane][1] = l1;
    __syncthreads();

    if (threadIdx.x < 32) {
        int bb = blockIdx.x * 32 + threadIdx.x;
        float s0 = wsm[1028], s1 = wsm[1029];
#pragma unroll
        for (int g = 0; g < 8; g++) { s0 += red[g][threadIdx.x][0]; s1 += red[g][threadIdx.x][1]; }
        float i0 = info[2 * bb], i1 = info[2 * bb + 1];
        s0 += i0 * wsm[512 * 2]     + i1 * wsm[513 * 2];
        s1 += i0 * wsm[512 * 2 + 1] + i1 * wsm[513 * 2 + 1];
        float m = fmaxf(s0, s1);
        float e0 = __expf(s0 - m), e1 = __expf(s1 - m);
        float inv = 1.0f / (e0 + e1);
        ((float2*)out)[bb] = make_float2(e0 * inv, e1 * inv);
    }
}

extern "C" void kernel_launch(void* const* d_in, const int* in_sizes, int n_in,
                              void* d_out, int out_size) {
    const float* x    = (const float*)d_in[0];
    const float* info = (const float*)d_in[1];
    const float* W0   = (const float*)d_in[2];
    const float* B0   = (const float*)d_in[3];
    const float* W1   = (const float*)d_in[4];
    const float* B1   = (const float*)d_in[5];
    const float* W2   = (const float*)d_in[6];
    const float* B2   = (const float*)d_in[7];
    const float* Wc   = (const float*)d_in[8];
    const float* bc   = (const float*)d_in[9];
    float* out = (float*)d_out;

    // Dynamic smem sizes: A tile + duplicated W tile
    const int s_l0 = (27 * 256) * 4 + (32 * 27) * 8;   // 27648 + 6912  = 34560
    const int s_l1 = (32 * 256) * 4 + (32 * 32) * 8;   // 32768 + 8192  = 40960
    const int s_l2 = (40 * 256) * 4 + (32 * 40) * 8;   // 40960 + 10240 = 51200
    cudaFuncSetAttribute(k_l0, cudaFuncAttributeMaxDynamicSharedMemorySize, s_l0);
    cudaFuncSetAttribute(k_l1, cudaFuncAttributeMaxDynamicSharedMemorySize, s_l1);
    cudaFuncSetAttribute(k_l2, cudaFuncAttributeMaxDynamicSharedMemorySize, s_l2);

    im2col_k<<<dim3(360, 128), 256>>>(x);
    k_l0<<<dim3(400, 16, 1), 256, s_l0>>>(W0, B0);     // 6400 blocks
    k_l1<<<dim3(100, 16, 2), 256, s_l1>>>(W1, B1);     // 3200 blocks
    k_l2<<<dim3(4, 16, 32), 256, s_l2>>>(W2, B2);      // 2048 blocks (4 cout x 8 kz)
    l2_combine_k<<<4 * 128 * 4096 / 4 / 256, 256>>>(B2);
    classifier_k<<<128, 256>>>(info, Wc, bc, out);
}

// round 5
// speedup vs baseline: 1.1283x; 1.1283x over previous
#include <cuda_runtime.h>
#include <cuda_bf16.h>
#include <cstdint>

// Scratch in static device memory. Layouts: [location][channel/k][batch], batch innermost.
__device__ float g_P0[400 * 54 * 4096];      // im2col of x
__device__ float g_H0[400 * 32 * 4096];      // layer0 out
__device__ float g_H1[100 * 64 * 4096];      // layer1 out
__device__ float g_H2[4 * 128 * 4096];       // layer2 out
__device__ float g_PART[4 * 4 * 128 * 4096]; // layer2 split-K partials [kz][loc][co][b]

static __device__ __forceinline__ float tanhap(float x) {
    float y; asm("tanh.approx.f32 %0, %1;" : "=f"(y) : "f"(x)); return y;
}
static __device__ __forceinline__ unsigned long long pack2(float w) {
    unsigned long long p; asm("mov.b64 %0, {%1, %1};" : "=l"(p) : "f"(w)); return p;
}
static __device__ __forceinline__ void ffma2(unsigned long long& acc,
                                             unsigned long long a, unsigned long long w2) {
    asm("fma.rn.f32x2 %0, %1, %2, %0;" : "+l"(acc) : "l"(a), "l"(w2));
}
static __device__ __forceinline__ void cpa16(void* s, const void* g) {
    uint32_t sa = (uint32_t)__cvta_generic_to_shared(s);
    asm volatile("cp.async.ca.shared.global [%0], [%1], 16;" :: "r"(sa), "l"(g));
}
static __device__ __forceinline__ void cpa4(void* s, const void* g) {
    uint32_t sa = (uint32_t)__cvta_generic_to_shared(s);
    asm volatile("cp.async.ca.shared.global [%0], [%1], 4;" :: "r"(sa), "l"(g));
}
static __device__ __forceinline__ void cpa_commit() {
    asm volatile("cp.async.commit_group;");
}
static __device__ __forceinline__ void cpa_wait_all() {
    asm volatile("cp.async.wait_group 0;");
}

// ---------------------------------------------------------------------------
// im2col: x[B,6,60,60] -> g_P0[loc][k][B]
// ---------------------------------------------------------------------------
__global__ void __launch_bounds__(256) im2col_k(const float* __restrict__ x) {
    const int ch = blockIdx.x;          // 0..359
    const int c = ch / 60, h = ch % 60;
    const int b0 = blockIdx.y * 32;
    __shared__ float s[32 * 61];
    const float* src = x + ((size_t)b0 * 6 + c) * 3600 + (size_t)h * 60;
    for (int e = threadIdx.x; e < 32 * 60; e += 256) {
        int bl = e / 60, w = e - bl * 60;
        s[bl * 61 + w] = src[(size_t)bl * 21600 + w];
    }
    __syncthreads();
    const int i = h / 3, dh = h % 3;
    for (int e = threadIdx.x; e < 32 * 60; e += 256) {
        int w = e >> 5, bl = e & 31;
        int j = w / 3, dw = w - j * 3;
        g_P0[((size_t)(i * 20 + j) * 54 + c * 9 + dh * 3 + dw) * 4096 + b0 + bl] =
            s[bl * 61 + w];
    }
}

// ---------------------------------------------------------------------------
// Locally-connected GEMM, 2-stage cp.async pipeline. 256 threads.
// Tile: BB batches x COUT_BLK couts; thread tile NC=COUT_BLK/8 x NB2=BB/64
// u64 accumulators (16 total). Weights scalar in smem + pack2 (R2 mix).
// Pipeline: prefetch(i+1) issued AFTER barrier(i) => copy(i+1) overlaps
// compute(i); stage reuse is one barrier later => no WAR hazard.
// ---------------------------------------------------------------------------
template <int CIN, int KH, int KW, int WIN, int WOUT, int COUT, int COUT_BLK,
          int KCHUNK, int BB, int KSPLIT, bool PARTIAL, int KZSTRIDE, bool W16>
static __device__ __forceinline__ void lc_gemm_body(const float* __restrict__ in,
                                                    const float* __restrict__ W,
                                                    const float* __restrict__ bias,
                                                    float* __restrict__ out) {
    constexpr int K      = CIN * KH * KW;
    constexpr int KPER   = K / KSPLIT;
    constexpr int NCHUNK = KPER / KCHUNK;
    constexpr int NC     = COUT_BLK / 8;
    constexpr int NB2    = BB / 64;
    constexpr int B      = 4096;

    __shared__ __align__(16) float as[2][KCHUNK * BB];
    __shared__ __align__(16) float ws[2][COUT_BLK * KCHUNK];

    const int loc = blockIdx.x;
    const int i = loc / WOUT, j = loc - i * WOUT;
    const int b0 = blockIdx.y * BB;
    const int cz = (blockIdx.z / KSPLIT) * COUT_BLK;
    const int kz = blockIdx.z % KSPLIT;
    const int t = threadIdx.x;
    const int lane = t & 31;
    const int cgrp = t >> 5;

    const float* Wl = W + ((size_t)loc * COUT + cz) * K;
    float* ob = out + (size_t)kz * KZSTRIDE;
    const int kbeg = kz * KPER;

    auto load_stage = [&](int st, int k0) {
        // A tile: rows contiguous in `in`, 16B-aligned (B=4096 stride)
        for (int id = t; id < KCHUNK * BB / 4; id += 256) {
            int kc = id / (BB / 4), off = (id % (BB / 4)) * 4;
            int k = k0 + kc;
            int c = k / (KH * KW);
            int r = k - c * (KH * KW);
            int dh = r / KW, dw = r - dh * KW;
            int loc_in = (KH * i + dh) * WIN + KW * j + dw;
            cpa16(&as[st][kc * BB + off],
                  in + ((size_t)loc_in * CIN + c) * B + b0 + off);
        }
        // W tile
        if (W16) {
            for (int id = t; id < COUT_BLK * KCHUNK / 4; id += 256) {
                int co = id / (KCHUNK / 4), off = (id % (KCHUNK / 4)) * 4;
                cpa16(&ws[st][co * KCHUNK + off], Wl + (size_t)co * K + k0 + off);
            }
        } else {
            for (int id = t; id < COUT_BLK * KCHUNK; id += 256) {
                int co = id / KCHUNK, kc = id - co * KCHUNK;
                cpa4(&ws[st][id], Wl + (size_t)co * K + k0 + kc);
            }
        }
        cpa_commit();
    };

    unsigned long long acc[NC][NB2];
#pragma unroll
    for (int c = 0; c < NC; c++) {
        unsigned long long p = PARTIAL ? 0ull
            : pack2(bias[(size_t)loc * COUT + cz + cgrp * NC + c]);
#pragma unroll
        for (int p2 = 0; p2 < NB2; p2++) acc[c][p2] = p;
    }

    load_stage(0, kbeg);
    for (int ch = 0; ch < NCHUNK; ch++) {
        cpa_wait_all();
        __syncthreads();
        if (ch + 1 < NCHUNK) load_stage((ch + 1) & 1, kbeg + (ch + 1) * KCHUNK);

        const int st = ch & 1;
        const unsigned long long* a2 = (const unsigned long long*)as[st];
        const float* wsp = ws[st];
#pragma unroll 2
        for (int kc = 0; kc < KCHUNK; kc++) {
            unsigned long long a[NB2];
#pragma unroll
            for (int p = 0; p < NB2; p++) a[p] = a2[kc * (BB / 2) + p * 32 + lane];
#pragma unroll
            for (int c = 0; c < NC; c++) {
                unsigned long long w2 = pack2(wsp[(cgrp * NC + c) * KCHUNK + kc]);
#pragma unroll
                for (int p = 0; p < NB2; p++) ffma2(acc[c][p], a[p], w2);
            }
        }
        // no trailing sync: next iteration's barrier orders reuse
    }

#pragma unroll
    for (int c = 0; c < NC; c++) {
        size_t obase = ((size_t)loc * COUT + cz + cgrp * NC + c) * B + b0;
#pragma unroll
        for (int p = 0; p < NB2; p++) {
            float x0, x1;
            asm("mov.b64 {%0, %1}, %2;" : "=f"(x0), "=f"(x1) : "l"(acc[c][p]));
            if (!PARTIAL) { x0 = tanhap(x0); x1 = tanhap(x1); }
            ((float2*)(ob + obase + p * 64))[lane] = make_float2(x0, x1);
        }
    }
}

// L0: K=54 over g_P0, BB=256, COUT_BLK=32 (NC=4 x NB2=4), KCHUNK=18 (3 chunks).
// smem 2*(18*256*4 + 32*18*4) = 41472
__global__ void __launch_bounds__(256, 3) k_l0(const float* __restrict__ W,
                                               const float* __restrict__ b) {
    lc_gemm_body<54, 1, 1, 20, 20, 32, 32, 18, 256, 1, false, 0, false>(g_P0, W, b, g_H0);
}
// L1: K=128, BB=128, COUT_BLK=64 (NC=8 x NB2=2), KCHUNK=32 (4 chunks).
// smem 2*(32*128*4 + 64*32*4) = 49152
__global__ void __launch_bounds__(256, 3) k_l1(const float* __restrict__ W,
                                               const float* __restrict__ b) {
    lc_gemm_body<32, 2, 2, 20, 10, 64, 64, 32, 128, 1, false, 0, true>(g_H0, W, b, g_H1);
}
// L2: K=1600, split-K=4 (KPER=400), BB=128, COUT_BLK=64, KCHUNK=20 (20 chunks).
// smem 2*(20*128*4 + 64*20*4) = 30720
__global__ void __launch_bounds__(256, 3) k_l2(const float* __restrict__ W,
                                               const float* __restrict__ b) {
    lc_gemm_body<64, 5, 5, 10, 2, 128, 64, 20, 128, 4, true, 4 * 128 * 4096, true>(
        g_H1, W, b, g_PART);
}

// Reduce 4 split-K partials + bias + tanh -> g_H2 (float4 per thread)
__global__ void __launch_bounds__(256) l2_combine_k(const float* __restrict__ B2) {
    constexpr int ST4 = 4 * 128 * 4096 / 4;
    int idx4 = blockIdx.x * 256 + threadIdx.x;
    int row = idx4 >> 10;                         // loc*128+co
    const float4* p = (const float4*)g_PART;
    float4 s = p[idx4];
#pragma unroll
    for (int z = 1; z < 4; z++) {
        float4 v = p[idx4 + z * ST4];
        s.x += v.x; s.y += v.y; s.z += v.z; s.w += v.w;
    }
    float bv = B2[row];
    ((float4*)g_H2)[idx4] = make_float4(tanhap(s.x + bv), tanhap(s.y + bv),
                                        tanhap(s.z + bv), tanhap(s.w + bv));
}

// ---------------------------------------------------------------------------
// Classifier + softmax. 128 blocks x 256 threads: 32 batches x 8 f-groups.
// ---------------------------------------------------------------------------
__global__ void __launch_bounds__(256) classifier_k(const float* __restrict__ info,
                                                    const float* __restrict__ Wc,
                                                    const float* __restrict__ bc,
                                                    float* __restrict__ out) {
    __shared__ float wsm[1030];
    __shared__ float red[8][32][2];
    for (int e = threadIdx.x; e < 1028; e += 256) wsm[e] = Wc[e];
    if (threadIdx.x < 2) wsm[1028 + threadIdx.x] = bc[threadIdx.x];
    __syncthreads();

    const int fg = threadIdx.x >> 5, lane = threadIdx.x & 31;
    const int b = blockIdx.x * 32 + lane;
    float l0 = 0.f, l1 = 0.f;
#pragma unroll 8
    for (int ff = 0; ff < 64; ff++) {
        int f = fg * 64 + ff;
        int row = (f & 3) * 128 + (f >> 2);
        float hv = g_H2[(size_t)row * 4096 + b];
        l0 += hv * wsm[f * 2];
        l1 += hv * wsm[f * 2 + 1];
    }
    red[fg][lane][0] = l0;
    red[fg][lane][1] = l1;
    __syncthreads();

    if (threadIdx.x < 32) {
        int bb = blockIdx.x * 32 + threadIdx.x;
        float s0 = wsm[1028], s1 = wsm[1029];
#pragma unroll
        for (int g = 0; g < 8; g++) { s0 += red[g][threadIdx.x][0]; s1 += red[g][threadIdx.x][1]; }
        float i0 = info[2 * bb], i1 = info[2 * bb + 1];
        s0 += i0 * wsm[512 * 2]     + i1 * wsm[513 * 2];
        s1 += i0 * wsm[512 * 2 + 1] + i1 * wsm[513 * 2 + 1];
        float m = fmaxf(s0, s1);
        float e0 = __expf(s0 - m), e1 = __expf(s1 - m);
        float inv = 1.0f / (e0 + e1);
        ((float2*)out)[bb] = make_float2(e0 * inv, e1 * inv);
    }
}

extern "C" void kernel_launch(void* const* d_in, const int* in_sizes, int n_in,
                              void* d_out, int out_size) {
    const float* x    = (const float*)d_in[0];
    const float* info = (const float*)d_in[1];
    const float* W0   = (const float*)d_in[2];
    const float* B0   = (const float*)d_in[3];
    const float* W1   = (const float*)d_in[4];
    const float* B1   = (const float*)d_in[5];
    const float* W2   = (const float*)d_in[6];
    const float* B2   = (const float*)d_in[7];
    const float* Wc   = (const float*)d_in[8];
    const float* bc   = (const float*)d_in[9];
    float* out = (float*)d_out;

    im2col_k<<<dim3(360, 128), 256>>>(x);
    k_l0<<<dim3(400, 16, 1), 256>>>(W0, B0);     // 6400 blocks
    k_l1<<<dim3(100, 32, 1), 256>>>(W1, B1);     // 3200 blocks
    k_l2<<<dim3(4, 32, 8), 256>>>(W2, B2);       // 1024 blocks (2 cout x 4 kz)
    l2_combine_k<<<4 * 128 * 4096 / 4 / 256, 256>>>(B2);
    classifier_k<<<128, 256>>>(info, Wc, bc, out);
}

// round 6
// speedup vs baseline: 1.5148x; 1.3426x over previous
#include <cuda_runtime.h>
#include <cuda_bf16.h>
#include <cstdint>

// Scratch in static device memory. Layouts: [location][channel/k][batch], batch innermost.
// P0 has K-stride 56 (rows 54,55 are never written -> stay zero = tf32 K-padding).
__device__ float g_P0[400 * 56 * 4096];      // im2col of x (padded K)
__device__ float g_H0[400 * 32 * 4096];      // layer0 out
__device__ float g_H1[100 * 64 * 4096];      // layer1 out
__device__ float g_H2[4 * 128 * 4096];       // layer2 out
__device__ float g_PART[4 * 4 * 128 * 4096]; // layer2 split-K partials [kz][loc][co][b]

static __device__ __forceinline__ float tanhap(float x) {
    float y; asm("tanh.approx.f32 %0, %1;" : "=f"(y) : "f"(x)); return y;
}
static __device__ __forceinline__ uint32_t f2tf(float f) {
    uint32_t r; asm("cvt.rna.tf32.f32 %0, %1;" : "=r"(r) : "f"(f)); return r;
}
static __device__ __forceinline__ void mma_tf32(float* d, uint32_t a0, uint32_t a1,
                                                uint32_t a2, uint32_t a3,
                                                uint32_t b0, uint32_t b1) {
    asm volatile(
        "mma.sync.aligned.m16n8k8.row.col.f32.tf32.tf32.f32 "
        "{%0,%1,%2,%3}, {%4,%5,%6,%7}, {%8,%9}, {%0,%1,%2,%3};"
        : "+f"(d[0]), "+f"(d[1]), "+f"(d[2]), "+f"(d[3])
        : "r"(a0), "r"(a1), "r"(a2), "r"(a3), "r"(b0), "r"(b1));
}
static __device__ __forceinline__ void cpa16(void* s, const void* g) {
    uint32_t sa = (uint32_t)__cvta_generic_to_shared(s);
    asm volatile("cp.async.ca.shared.global [%0], [%1], 16;" :: "r"(sa), "l"(g));
}
static __device__ __forceinline__ void cpa4(void* s, const void* g) {
    uint32_t sa = (uint32_t)__cvta_generic_to_shared(s);
    asm volatile("cp.async.ca.shared.global [%0], [%1], 4;" :: "r"(sa), "l"(g));
}
static __device__ __forceinline__ void cpa_commit() {
    asm volatile("cp.async.commit_group;");
}
static __device__ __forceinline__ void cpa_wait_all() {
    asm volatile("cp.async.wait_group 0;");
}

// ---------------------------------------------------------------------------
// im2col: x[B,6,60,60] -> g_P0[loc][k(56-stride)][B]
// ---------------------------------------------------------------------------
__global__ void __launch_bounds__(256) im2col_k(const float* __restrict__ x) {
    const int ch = blockIdx.x;          // 0..359
    const int c = ch / 60, h = ch % 60;
    const int b0 = blockIdx.y * 32;
    __shared__ float s[32 * 61];
    const float* src = x + ((size_t)b0 * 6 + c) * 3600 + (size_t)h * 60;
    for (int e = threadIdx.x; e < 32 * 60; e += 256) {
        int bl = e / 60, w = e - bl * 60;
        s[bl * 61 + w] = src[(size_t)bl * 21600 + w];
    }
    __syncthreads();
    const int i = h / 3, dh = h % 3;
    for (int e = threadIdx.x; e < 32 * 60; e += 256) {
        int w = e >> 5, bl = e & 31;
        int j = w / 3, dw = w - j * 3;
        g_P0[((size_t)(i * 20 + j) * 56 + c * 9 + dh * 3 + dw) * 4096 + b0 + bl] =
            s[bl * 61 + w];
    }
}

// ---------------------------------------------------------------------------
// Locally-connected GEMM on tf32 tensor cores (mma.sync m16n8k8).
// 256 threads = 8 warps. CTA tile: BB batches x COUT_BLK couts.
// Warp tile: 16 couts x 64 batches = 8 mma n-tiles (even/odd batch interleave
// per n-tile pair -> LDS.64 B fragments, conflict-free via stride 8 mod 32).
// W smem stride == 4 mod 8 -> conflict-free scalar A-fragment loads.
// Epilogue: acc -> smem (STS.128, reusing A buffer) -> coalesced global.
// ---------------------------------------------------------------------------
template <int CIN, int KH, int KW, int WIN, int WOUT, int COUT, int COUT_BLK,
          int KCHUNK, int BB, int KSPLIT, bool PARTIAL, long long KZSTRIDE,
          int KTOT, int KWG, int STAGES>
static __device__ __forceinline__ void lc_mma_body(const float* __restrict__ in,
                                                   const float* __restrict__ W,
                                                   const float* __restrict__ bias,
                                                   float* __restrict__ out) {
    constexpr int KPER   = KTOT / KSPLIT;
    constexpr int NCHUNK = KPER / KCHUNK;
    constexpr int AS     = BB + 8;           // A smem stride (== 8 mod 32)
    constexpr int WS     = KCHUNK + 4;       // W smem stride (== 4 mod 8)
    constexpr int NCOT   = COUT_BLK / 16;    // cout tiles
    constexpr int B      = 4096;

    extern __shared__ __align__(16) float dsm[];
    float* Asm = dsm;                            // [STAGES][KCHUNK][AS]
    float* Wsm = dsm + STAGES * KCHUNK * AS;     // [STAGES][COUT_BLK][WS]

    const int loc = blockIdx.x;
    const int i = loc / WOUT, j = loc - i * WOUT;
    const int b0 = blockIdx.y * BB;
    const int cz = (blockIdx.z / KSPLIT) * COUT_BLK;
    const int kz = blockIdx.z % KSPLIT;
    const int t = threadIdx.x;
    const int lane = t & 31;
    const int wid = t >> 5;
    const int qr = lane >> 2, qc = lane & 3;
    const int cot = wid % NCOT;         // cout tile of this warp
    const int bg  = wid / NCOT;         // 64-batch group of this warp

    const float* Wl = W + ((size_t)loc * COUT + cz) * KWG;
    float* ob = out + (size_t)kz * KZSTRIDE;
    const int kbeg = kz * KPER;

    auto load_stage = [&](int st, int k0) {
        float* As = Asm + st * KCHUNK * AS;
        float* Ws = Wsm + st * COUT_BLK * WS;
        // A tile: rows contiguous in `in` (batch-innermost), 16B aligned
        for (int id = t; id < KCHUNK * BB / 4; id += 256) {
            int kc = id / (BB / 4), off = (id % (BB / 4)) * 4;
            int k = k0 + kc;
            int c = k / (KH * KW);
            int r = k - c * (KH * KW);
            int dh = r / KW, dw = r - dh * KW;
            int loc_in = (KH * i + dh) * WIN + KW * j + dw;
            cpa16(&As[kc * AS + off],
                  in + ((size_t)loc_in * CIN + c) * B + b0 + off);
        }
        // W tile
        if (KWG == KTOT) {
            for (int id = t; id < COUT_BLK * KCHUNK / 4; id += 256) {
                int co = id / (KCHUNK / 4), off = (id % (KCHUNK / 4)) * 4;
                cpa16(&Ws[co * WS + off], Wl + (size_t)co * KWG + k0 + off);
            }
        } else {  // K padded: per-element with zero fill
            for (int id = t; id < COUT_BLK * KCHUNK; id += 256) {
                int co = id / KCHUNK, kc = id - co * KCHUNK;
                if (k0 + kc < KWG) cpa4(&Ws[co * WS + kc], Wl + (size_t)co * KWG + k0 + kc);
                else Ws[co * WS + kc] = 0.0f;
            }
        }
        cpa_commit();
    };

    float acc[8][4];   // [n-tile][reg], n-tile = pair*2 + (odd batches)
#pragma unroll
    for (int nt = 0; nt < 8; nt++)
#pragma unroll
        for (int r = 0; r < 4; r++) acc[nt][r] = 0.0f;

    load_stage(0, kbeg);
    for (int ch = 0; ch < NCHUNK; ch++) {
        cpa_wait_all();
        __syncthreads();
        if (STAGES == 2 && ch + 1 < NCHUNK)
            load_stage((ch + 1) & 1, kbeg + (ch + 1) * KCHUNK);

        const int st = (STAGES == 2) ? (ch & 1) : 0;
        const float* As = Asm + st * KCHUNK * AS;
        const float* Ws = Wsm + st * COUT_BLK * WS;

#pragma unroll
        for (int kk = 0; kk < KCHUNK; kk += 8) {
            const float* wrow = Ws + (cot * 16 + qr) * WS + kk + qc;
            uint32_t a0 = f2tf(wrow[0]);
            uint32_t a1 = f2tf(wrow[8 * WS]);
            uint32_t a2 = f2tf(wrow[4]);
            uint32_t a3 = f2tf(wrow[8 * WS + 4]);
            const float* ar0 = As + (kk + qc) * AS + bg * 64;
            const float* ar1 = ar0 + 4 * AS;
#pragma unroll
            for (int p = 0; p < 4; p++) {
                float2 v0 = *(const float2*)(ar0 + p * 16 + 2 * qr);
                float2 v1 = *(const float2*)(ar1 + p * 16 + 2 * qr);
                uint32_t b0E = f2tf(v0.x), b0O = f2tf(v0.y);
                uint32_t b1E = f2tf(v1.x), b1O = f2tf(v1.y);
                mma_tf32(acc[p * 2 + 0], a0, a1, a2, a3, b0E, b1E);
                mma_tf32(acc[p * 2 + 1], a0, a1, a2, a3, b0O, b1O);
            }
        }
        if (STAGES == 1) break;
    }

    // Epilogue: stage to smem (reuse A buffer), then coalesced global writes.
    __syncthreads();
    constexpr int DS = BB + 8;
    float* Dsm = dsm;
#pragma unroll
    for (int p = 0; p < 4; p++) {
        int base = bg * 64 + p * 16 + 4 * qc;
        int row0 = cot * 16 + qr;
        // c0E,c0O,c1E,c1O -> batches base..base+3 on row0; c2..c3 on row0+8
        *(float4*)&Dsm[row0 * DS + base] =
            make_float4(acc[2 * p][0], acc[2 * p + 1][0], acc[2 * p][1], acc[2 * p + 1][1]);
        *(float4*)&Dsm[(row0 + 8) * DS + base] =
            make_float4(acc[2 * p][2], acc[2 * p + 1][2], acc[2 * p][3], acc[2 * p + 1][3]);
    }
    __syncthreads();

    for (int idx = t; idx < COUT_BLK * BB; idx += 256) {
        int co = idx / BB, bl = idx - co * BB;
        float v = Dsm[co * DS + bl];
        if (!PARTIAL) v = tanhap(v + bias[(size_t)loc * COUT + cz + co]);
        ob[((size_t)loc * COUT + cz + co) * B + b0 + bl] = v;
    }
}

// L0: K=54 (padded 56), single chunk. BB=256, COUT_BLK=32.
__global__ void __launch_bounds__(256) k_l0(const float* __restrict__ W,
                                            const float* __restrict__ b) {
    lc_mma_body<56, 1, 1, 20, 20, 32, 32, 56, 256, 1, false, 0, 56, 54, 1>(
        g_P0, W, b, g_H0);
}
// L1: K=128, KCHUNK=32, 4 chunks, 2-stage. BB=128, COUT_BLK=64.
__global__ void __launch_bounds__(256) k_l1(const float* __restrict__ W,
                                            const float* __restrict__ b) {
    lc_mma_body<32, 2, 2, 20, 10, 64, 64, 32, 128, 1, false, 0, 128, 128, 2>(
        g_H0, W, b, g_H1);
}
// L2: K=1600, split-K=4 (KPER=400), KCHUNK=40, 10 chunks, 2-stage.
__global__ void __launch_bounds__(256) k_l2(const float* __restrict__ W,
                                            const float* __restrict__ b) {
    lc_mma_body<64, 5, 5, 10, 2, 128, 64, 40, 128, 4, true, 4LL * 128 * 4096,
                1600, 1600, 2>(g_H1, W, b, g_PART);
}

// Reduce 4 split-K partials + bias + tanh -> g_H2 (float4 per thread)
__global__ void __launch_bounds__(256) l2_combine_k(const float* __restrict__ B2) {
    constexpr int ST4 = 4 * 128 * 4096 / 4;
    int idx4 = blockIdx.x * 256 + threadIdx.x;
    int row = idx4 >> 10;                         // loc*128+co
    const float4* p = (const float4*)g_PART;
    float4 s = p[idx4];
#pragma unroll
    for (int z = 1; z < 4; z++) {
        float4 v = p[idx4 + z * ST4];
        s.x += v.x; s.y += v.y; s.z += v.z; s.w += v.w;
    }
    float bv = B2[row];
    ((float4*)g_H2)[idx4] = make_float4(tanhap(s.x + bv), tanhap(s.y + bv),
                                        tanhap(s.z + bv), tanhap(s.w + bv));
}

// ---------------------------------------------------------------------------
// Classifier + softmax. 128 blocks x 256 threads: 32 batches x 8 f-groups.
// ---------------------------------------------------------------------------
__global__ void __launch_bounds__(256) classifier_k(const float* __restrict__ info,
                                                    const float* __restrict__ Wc,
                                                    const float* __restrict__ bc,
                                                    float* __restrict__ out) {
    __shared__ float wsm[1030];
    __shared__ float red[8][32][2];
    for (int e = threadIdx.x; e < 1028; e += 256) wsm[e] = Wc[e];
    if (threadIdx.x < 2) wsm[1028 + threadIdx.x] = bc[threadIdx.x];
    __syncthreads();

    const int fg = threadIdx.x >> 5, lane = threadIdx.x & 31;
    const int b = blockIdx.x * 32 + lane;
    float l0 = 0.f, l1 = 0.f;
#pragma unroll 8
    for (int ff = 0; ff < 64; ff++) {
        int f = fg * 64 + ff;
        int row = (f & 3) * 128 + (f >> 2);
        float hv = g_H2[(size_t)row * 4096 + b];
        l0 += hv * wsm[f * 2];
        l1 += hv * wsm[f * 2 + 1];
    }
    red[fg][lane][0] = l0;
    red[fg][lane][1] = l1;
    __syncthreads();

    if (threadIdx.x < 32) {
        int bb = blockIdx.x * 32 + threadIdx.x;
        float s0 = wsm[1028], s1 = wsm[1029];
#pragma unroll
        for (int g = 0; g < 8; g++) { s0 += red[g][threadIdx.x][0]; s1 += red[g][threadIdx.x][1]; }
        float i0 = info[2 * bb], i1 = info[2 * bb + 1];
        s0 += i0 * wsm[512 * 2]     + i1 * wsm[513 * 2];
        s1 += i0 * wsm[512 * 2 + 1] + i1 * wsm[513 * 2 + 1];
        float m = fmaxf(s0, s1);
        float e0 = __expf(s0 - m), e1 = __expf(s1 - m);
        float inv = 1.0f / (e0 + e1);
        ((float2*)out)[bb] = make_float2(e0 * inv, e1 * inv);
    }
}

extern "C" void kernel_launch(void* const* d_in, const int* in_sizes, int n_in,
                              void* d_out, int out_size) {
    const float* x    = (const float*)d_in[0];
    const float* info = (const float*)d_in[1];
    const float* W0   = (const float*)d_in[2];
    const float* B0   = (const float*)d_in[3];
    const float* W1   = (const float*)d_in[4];
    const float* B1   = (const float*)d_in[5];
    const float* W2   = (const float*)d_in[6];
    const float* B2   = (const float*)d_in[7];
    const float* Wc   = (const float*)d_in[8];
    const float* bc   = (const float*)d_in[9];
    float* out = (float*)d_out;

    // Dynamic smem: STAGES*(KCHUNK*AS) + STAGES*(COUT_BLK*WS) floats
    const int s_l0 = (56 * 264 + 32 * 60) * 4;              // 59136 + 7680  = 66816
    const int s_l1 = 2 * (32 * 136 + 64 * 36) * 4;          // 34816 + 18432 = 53248
    const int s_l2 = 2 * (40 * 136 + 64 * 44) * 4;          // 43520 + 22528 = 66048
    cudaFuncSetAttribute(k_l0, cudaFuncAttributeMaxDynamicSharedMemorySize, s_l0);
    cudaFuncSetAttribute(k_l1, cudaFuncAttributeMaxDynamicSharedMemorySize, s_l1);
    cudaFuncSetAttribute(k_l2, cudaFuncAttributeMaxDynamicSharedMemorySize, s_l2);

    im2col_k<<<dim3(360, 128), 256>>>(x);
    k_l0<<<dim3(400, 16, 1), 256, s_l0>>>(W0, B0);   // 6400 CTAs
    k_l1<<<dim3(100, 32, 1), 256, s_l1>>>(W1, B1);   // 3200 CTAs
    k_l2<<<dim3(4, 32, 8), 256, s_l2>>>(W2, B2);     // 1024 CTAs (2 co x 4 kz)
    l2_combine_k<<<4 * 128 * 4096 / 4 / 256, 256>>>(B2);
    classifier_k<<<128, 256>>>(info, Wc, bc, out);
}

// round 8
// speedup vs baseline: 1.5278x; 1.0086x over previous
#include <cuda_runtime.h>
#include <cuda_bf16.h>
#include <cstdint>

// Scratch in static device memory. Layouts: [location][channel/k][batch], batch innermost.
// All MMA-consumed activations are stored PRE-ROUNDED to tf32 bit patterns.
// P0 has K-stride 56 (rows 54,55 never written -> stay zero = tf32 K-padding).
__device__ float g_P0[400 * 56 * 4096];      // im2col of x (padded K, tf32)
__device__ float g_H0[400 * 32 * 4096];      // layer0 out (tf32)
__device__ float g_H1[100 * 64 * 4096];      // layer1 out (tf32)
__device__ float g_H2[4 * 128 * 4096];       // layer2 out (fp32, classifier input)
__device__ float g_PART[4 * 4 * 128 * 4096]; // layer2 split-K partials
// Pre-converted (tf32-rounded) weights:
__device__ float g_W0c[400 * 32 * 56];       // K padded 54->56, zero fill
__device__ float g_W1c[100 * 64 * 128];
__device__ float g_W2c[4 * 128 * 1600];

static __device__ __forceinline__ float tanhap(float x) {
    float y; asm("tanh.approx.f32 %0, %1;" : "=f"(y) : "f"(x)); return y;
}
static __device__ __forceinline__ uint32_t f2tf(float f) {
    uint32_t r; asm("cvt.rna.tf32.f32 %0, %1;" : "=r"(r) : "f"(f)); return r;
}
static __device__ __forceinline__ float tfround(float f) {
    return __uint_as_float(f2tf(f));
}
static __device__ __forceinline__ void mma_tf32(float* d, uint32_t a0, uint32_t a1,
                                                uint32_t a2, uint32_t a3,
                                                uint32_t b0, uint32_t b1) {
    asm volatile(
        "mma.sync.aligned.m16n8k8.row.col.f32.tf32.tf32.f32 "
        "{%0,%1,%2,%3}, {%4,%5,%6,%7}, {%8,%9}, {%0,%1,%2,%3};"
        : "+f"(d[0]), "+f"(d[1]), "+f"(d[2]), "+f"(d[3])
        : "r"(a0), "r"(a1), "r"(a2), "r"(a3), "r"(b0), "r"(b1));
}
static __device__ __forceinline__ void cpa16(void* s, const void* g) {
    uint32_t sa = (uint32_t)__cvta_generic_to_shared(s);
    asm volatile("cp.async.ca.shared.global [%0], [%1], 16;" :: "r"(sa), "l"(g));
}
static __device__ __forceinline__ void cpa_commit() {
    asm volatile("cp.async.commit_group;");
}
static __device__ __forceinline__ void cpa_wait_all() {
    asm volatile("cp.async.wait_group 0;");
}

// ---------------------------------------------------------------------------
// Weight pre-conversion (tf32 round). W0 also re-laid-out to K-stride 56.
// ---------------------------------------------------------------------------
__global__ void __launch_bounds__(256) wconv0_k(const float* __restrict__ W0) {
    int idx = blockIdx.x * 256 + threadIdx.x;        // over 400*32*56
    if (idx >= 400 * 32 * 56) return;
    int k = idx % 56, row = idx / 56;                // row = loc*32+co
    g_W0c[idx] = (k < 54) ? tfround(W0[row * 54 + k]) : 0.0f;
}
__global__ void __launch_bounds__(256) wconv_k(const float* __restrict__ src,
                                               float* __restrict__ dst, int n) {
    int idx = blockIdx.x * 256 + threadIdx.x;
    if (idx < n) dst[idx] = tfround(src[idx]);
}

// ---------------------------------------------------------------------------
// im2col: x[B,6,60,60] -> g_P0[loc][k(56-stride)][B], tf32-rounded.
// ---------------------------------------------------------------------------
__global__ void __launch_bounds__(256) im2col_k(const float* __restrict__ x) {
    const int ch = blockIdx.x;          // 0..359
    const int c = ch / 60, h = ch % 60;
    const int b0 = blockIdx.y * 32;
    __shared__ float s[32 * 61];
    const float* src = x + ((size_t)b0 * 6 + c) * 3600 + (size_t)h * 60;
    for (int e = threadIdx.x; e < 32 * 60; e += 256) {
        int bl = e / 60, w = e - bl * 60;
        s[bl * 61 + w] = src[(size_t)bl * 21600 + w];
    }
    __syncthreads();
    const int i = h / 3, dh = h % 3;
    for (int e = threadIdx.x; e < 32 * 60; e += 256) {
        int w = e >> 5, bl = e & 31;
        int j = w / 3, dw = w - j * 3;
        g_P0[((size_t)(i * 20 + j) * 56 + c * 9 + dh * 3 + dw) * 4096 + b0 + bl] =
            tfround(s[bl * 61 + w]);
    }
}

// ---------------------------------------------------------------------------
// Locally-connected GEMM on tf32 tensor cores (mma.sync m16n8k8).
// 256 threads = 8 warps. CTA tile: BB batches x COUT_BLK couts.
// All operands pre-rounded -> inner loop is pure LDS + MMA (no CVT).
// ---------------------------------------------------------------------------
template <int CIN, int KH, int KW, int WIN, int WOUT, int COUT, int COUT_BLK,
          int KCHUNK, int BB, int KSPLIT, bool PARTIAL, long long KZSTRIDE,
          int KTOT, int STAGES, bool ROUND_OUT>
static __device__ __forceinline__ void lc_mma_body(const float* __restrict__ in,
                                                   const float* __restrict__ W,
                                                   const float* __restrict__ bias,
                                                   float* __restrict__ out) {
    constexpr int KPER   = KTOT / KSPLIT;
    constexpr int NCHUNK = KPER / KCHUNK;
    constexpr int AS     = BB + 8;           // A smem stride (== 8 mod 32)
    constexpr int WS     = KCHUNK + 4;       // W smem stride (== 4 mod 8)
    constexpr int NCOT   = COUT_BLK / 16;    // cout tiles
    constexpr int B      = 4096;

    extern __shared__ __align__(16) float dsm[];
    float* Asm = dsm;                            // [STAGES][KCHUNK][AS]
    float* Wsm = dsm + STAGES * KCHUNK * AS;     // [STAGES][COUT_BLK][WS]

    const int loc = blockIdx.x;
    const int i = loc / WOUT, j = loc - i * WOUT;
    const int b0 = blockIdx.y * BB;
    const int cz = (blockIdx.z / KSPLIT) * COUT_BLK;
    const int kz = blockIdx.z % KSPLIT;
    const int t = threadIdx.x;
    const int lane = t & 31;
    const int wid = t >> 5;
    const int qr = lane >> 2, qc = lane & 3;
    const int cot = wid % NCOT;         // cout tile of this warp
    const int bg  = wid / NCOT;         // 64-batch group of this warp

    const float* Wl = W + ((size_t)loc * COUT + cz) * KTOT;
    float* ob = out + (size_t)kz * KZSTRIDE;
    const int kbeg = kz * KPER;

    auto load_stage = [&](int st, int k0) {
        float* As = Asm + st * KCHUNK * AS;
        float* Ws = Wsm + st * COUT_BLK * WS;
        for (int id = t; id < KCHUNK * BB / 4; id += 256) {
            int kc = id / (BB / 4), off = (id % (BB / 4)) * 4;
            int k = k0 + kc;
            int c = k / (KH * KW);
            int r = k - c * (KH * KW);
            int dh = r / KW, dw = r - dh * KW;
            int loc_in = (KH * i + dh) * WIN + KW * j + dw;
            cpa16(&As[kc * AS + off],
                  in + ((size_t)loc_in * CIN + c) * B + b0 + off);
        }
        for (int id = t; id < COUT_BLK * KCHUNK / 4; id += 256) {
            int co = id / (KCHUNK / 4), off = (id % (KCHUNK / 4)) * 4;
            cpa16(&Ws[co * WS + off], Wl + (size_t)co * KTOT + k0 + off);
        }
        cpa_commit();
    };

    float acc[8][4];
#pragma unroll
    for (int nt = 0; nt < 8; nt++)
#pragma unroll
        for (int r = 0; r < 4; r++) acc[nt][r] = 0.0f;

    load_stage(0, kbeg);
    for (int ch = 0; ch < NCHUNK; ch++) {
        cpa_wait_all();
        __syncthreads();
        if (STAGES == 2 && ch + 1 < NCHUNK)
            load_stage((ch + 1) & 1, kbeg + (ch + 1) * KCHUNK);

        const int st = (STAGES == 2) ? (ch & 1) : 0;
        const float* As = Asm + st * KCHUNK * AS;
        const float* Ws = Wsm + st * COUT_BLK * WS;

#pragma unroll
        for (int kk = 0; kk < KCHUNK; kk += 8) {
            const float* wrow = Ws + (cot * 16 + qr) * WS + kk + qc;
            uint32_t a0 = __float_as_uint(wrow[0]);
            uint32_t a1 = __float_as_uint(wrow[8 * WS]);
            uint32_t a2 = __float_as_uint(wrow[4]);
            uint32_t a3 = __float_as_uint(wrow[8 * WS + 4]);
            const float* ar0 = As + (kk + qc) * AS + bg * 64;
            const float* ar1 = ar0 + 4 * AS;
#pragma unroll
            for (int p = 0; p < 4; p++) {
                float2 v0 = *(const float2*)(ar0 + p * 16 + 2 * qr);
                float2 v1 = *(const float2*)(ar1 + p * 16 + 2 * qr);
                mma_tf32(acc[p * 2 + 0], a0, a1, a2, a3,
                         __float_as_uint(v0.x), __float_as_uint(v1.x));
                mma_tf32(acc[p * 2 + 1], a0, a1, a2, a3,
                         __float_as_uint(v0.y), __float_as_uint(v1.y));
            }
        }
        if (STAGES == 1) break;
    }

    // Epilogue: stage to smem (reuse A buffer), then coalesced global writes.
    __syncthreads();
    constexpr int DS = BB + 8;
    float* Dsm = dsm;
#pragma unroll
    for (int p = 0; p < 4; p++) {
        int base = bg * 64 + p * 16 + 4 * qc;
        int row0 = cot * 16 + qr;
        *(float4*)&Dsm[row0 * DS + base] =
            make_float4(acc[2 * p][0], acc[2 * p + 1][0], acc[2 * p][1], acc[2 * p + 1][1]);
        *(float4*)&Dsm[(row0 + 8) * DS + base] =
            make_float4(acc[2 * p][2], acc[2 * p + 1][2], acc[2 * p][3], acc[2 * p + 1][3]);
    }
    __syncthreads();

    for (int idx = t; idx < COUT_BLK * BB; idx += 256) {
        int co = idx / BB, bl = idx - co * BB;
        float v = Dsm[co * DS + bl];
        if (!PARTIAL) {
            v = tanhap(v + bias[(size_t)loc * COUT + cz + co]);
            if (ROUND_OUT) v = tfround(v);
        }
        ob[((size_t)loc * COUT + cz + co) * B + b0 + bl] = v;
    }
}

// L0: K=56 (padded), single chunk. BB=256, COUT_BLK=32. Output tf32-rounded.
__global__ void __launch_bounds__(256) k_l0(const float* __restrict__ W,
                                            const float* __restrict__ b) {
    lc_mma_body<56, 1, 1, 20, 20, 32, 32, 56, 256, 1, false, 0, 56, 1, true>(
        g_P0, W, b, g_H0);
}
// L1: K=128, KCHUNK=32, 4 chunks, 2-stage. BB=128, COUT_BLK=64. Output tf32.
__global__ void __launch_bounds__(256) k_l1(const float* __restrict__ W,
                                            const float* __restrict__ b) {
    lc_mma_body<32, 2, 2, 20, 10, 64, 64, 32, 128, 1, false, 0, 128, 2, true>(
        g_H0, W, b, g_H1);
}
// L2: K=1600, split-K=4 (KPER=400), KCHUNK=40, 10 chunks, 2-stage. Partials.
__global__ void __launch_bounds__(256) k_l2(const float* __restrict__ W,
                                            const float* __restrict__ b) {
    lc_mma_body<64, 5, 5, 10, 2, 128, 64, 40, 128, 4, true, 4LL * 128 * 4096,
                1600, 2, false>(g_H1, W, b, g_PART);
}

// Reduce 4 split-K partials + bias + tanh -> g_H2 (fp32, classifier input)
__global__ void __launch_bounds__(256) l2_combine_k(const float* __restrict__ B2) {
    constexpr int ST4 = 4 * 128 * 4096 / 4;
    int idx4 = blockIdx.x * 256 + threadIdx.x;
    int row = idx4 >> 10;                         // loc*128+co
    const float4* p = (const float4*)g_PART;
    float4 s = p[idx4];
#pragma unroll
    for (int z = 1; z < 4; z++) {
        float4 v = p[idx4 + z * ST4];
        s.x += v.x; s.y += v.y; s.z += v.z; s.w += v.w;
    }
    float bv = B2[row];
    ((float4*)g_H2)[idx4] = make_float4(tanhap(s.x + bv), tanhap(s.y + bv),
                                        tanhap(s.z + bv), tanhap(s.w + bv));
}

// ---------------------------------------------------------------------------
// Classifier + softmax. 128 blocks x 256 threads: 32 batches x 8 f-groups.
// ---------------------------------------------------------------------------
__global__ void __launch_bounds__(256) classifier_k(const float* __restrict__ info,
                                                    const float* __restrict__ Wc,
                                                    const float* __restrict__ bc,
                                                    float* __restrict__ out) {
    __shared__ float wsm[1030];
    __shared__ float red[8][32][2];
    for (int e = threadIdx.x; e < 1028; e += 256) wsm[e] = Wc[e];
    if (threadIdx.x < 2) wsm[1028 + threadIdx.x] = bc[threadIdx.x];
    __syncthreads();

    const int fg = threadIdx.x >> 5, lane = threadIdx.x & 31;
    const int b = blockIdx.x * 32 + lane;
    float l0 = 0.f, l1 = 0.f;
#pragma unroll 8
    for (int ff = 0; ff < 64; ff++) {
        int f = fg * 64 + ff;
        int row = (f & 3) * 128 + (f >> 2);
        float hv = g_H2[(size_t)row * 4096 + b];
        l0 += hv * wsm[f * 2];
        l1 += hv * wsm[f * 2 + 1];
    }
    red[fg][lane][0] = l0;
    red[fg][lane][1] = l1;
    __syncthreads();

    if (threadIdx.x < 32) {
        int bb = blockIdx.x * 32 + threadIdx.x;
        float s0 = wsm[1028], s1 = wsm[1029];
#pragma unroll
        for (int g = 0; g < 8; g++) { s0 += red[g][threadIdx.x][0]; s1 += red[g][threadIdx.x][1]; }
        float i0 = info[2 * bb], i1 = info[2 * bb + 1];
        s0 += i0 * wsm[512 * 2]     + i1 * wsm[513 * 2];
        s1 += i0 * wsm[512 * 2 + 1] + i1 * wsm[513 * 2 + 1];
        float m = fmaxf(s0, s1);
        float e0 = __expf(s0 - m), e1 = __expf(s1 - m);
        float inv = 1.0f / (e0 + e1);
        ((float2*)out)[bb] = make_float2(e0 * inv, e1 * inv);
    }
}

extern "C" void kernel_launch(void* const* d_in, const int* in_sizes, int n_in,
                              void* d_out, int out_size) {
    const float* x    = (const float*)d_in[0];
    const float* info = (const float*)d_in[1];
    const float* W0   = (const float*)d_in[2];
    const float* B0   = (const float*)d_in[3];
    const float* W1   = (const float*)d_in[4];
    const float* B1   = (const float*)d_in[5];
    const float* W2   = (const float*)d_in[6];
    const float* B2   = (const float*)d_in[7];
    const float* Wc   = (const float*)d_in[8];
    const float* bc   = (const float*)d_in[9];
    float* out = (float*)d_out;

    // Dynamic smem: STAGES*(KCHUNK*AS + COUT_BLK*WS) floats
    const int s_l0 = (56 * 264 + 32 * 60) * 4;              // 66816
    const int s_l1 = 2 * (32 * 136 + 64 * 36) * 4;          // 53248
    const int s_l2 = 2 * (40 * 136 + 64 * 44) * 4;          // 66048
    cudaFuncSetAttribute(k_l0, cudaFuncAttributeMaxDynamicSharedMemorySize, s_l0);
    cudaFuncSetAttribute(k_l1, cudaFuncAttributeMaxDynamicSharedMemorySize, s_l1);
    cudaFuncSetAttribute(k_l2, cudaFuncAttributeMaxDynamicSharedMemorySize, s_l2);

    // Resolve device-symbol scratch to REAL device pointers (host shadow of a
    // __device__ array is NOT a valid device pointer -- R7's bug).
    float* W0c; cudaGetSymbolAddress((void**)&W0c, g_W0c);
    float* W1c; cudaGetSymbolAddress((void**)&W1c, g_W1c);
    float* W2c; cudaGetSymbolAddress((void**)&W2c, g_W2c);

    wconv0_k<<<(400 * 32 * 56 + 255) / 256, 256>>>(W0);
    wconv_k<<<(100 * 64 * 128 + 255) / 256, 256>>>(W1, W1c, 100 * 64 * 128);
    wconv_k<<<(4 * 128 * 1600 + 255) / 256, 256>>>(W2, W2c, 4 * 128 * 1600);
    im2col_k<<<dim3(360, 128), 256>>>(x);
    k_l0<<<dim3(400, 16, 1), 256, s_l0>>>(W0c, B0);   // 6400 CTAs
    k_l1<<<dim3(100, 32, 1), 256, s_l1>>>(W1c, B1);   // 3200 CTAs
    k_l2<<<dim3(4, 32, 8), 256, s_l2>>>(W2c, B2);     // 1024 CTAs
    l2_combine_k<<<4 * 128 * 4096 / 4 / 256, 256>>>(B2);
    classifier_k<<<128, 256>>>(info, Wc, bc, out);
}

// round 9
// speedup vs baseline: 1.7268x; 1.1302x over previous
#include <cuda_runtime.h>
#include <cuda_bf16.h>
#include <cstdint>

// Scratch in static device memory. Layouts: [location][channel/k][batch], batch innermost.
// All MMA-consumed activations are stored PRE-ROUNDED to tf32 bit patterns.
// P0 has K-stride 56 (rows 54,55 never written -> stay zero = tf32 K-padding).
__device__ float g_P0[400 * 56 * 4096];      // im2col of x (padded K, tf32)
__device__ float g_H0[400 * 32 * 4096];      // layer0 out (tf32)
__device__ float g_H1[100 * 64 * 4096];      // layer1 out (tf32)
__device__ float g_H2[4 * 128 * 4096];       // layer2 out (fp32, classifier input)
__device__ float g_PART[4 * 4 * 128 * 4096]; // layer2 split-K partials
// Pre-converted (tf32-rounded) weights:
__device__ float g_W0c[400 * 32 * 56];       // K padded 54->56, zero fill
__device__ float g_W1c[100 * 64 * 128];
__device__ float g_W2c[4 * 128 * 1600];

static __device__ __forceinline__ float tanhap(float x) {
    float y; asm("tanh.approx.f32 %0, %1;" : "=f"(y) : "f"(x)); return y;
}
static __device__ __forceinline__ uint32_t f2tf(float f) {
    uint32_t r; asm("cvt.rna.tf32.f32 %0, %1;" : "=r"(r) : "f"(f)); return r;
}
static __device__ __forceinline__ float tfround(float f) {
    return __uint_as_float(f2tf(f));
}
static __device__ __forceinline__ void mma_tf32(float* d, uint32_t a0, uint32_t a1,
                                                uint32_t a2, uint32_t a3,
                                                uint32_t b0, uint32_t b1) {
    asm volatile(
        "mma.sync.aligned.m16n8k8.row.col.f32.tf32.tf32.f32 "
        "{%0,%1,%2,%3}, {%4,%5,%6,%7}, {%8,%9}, {%0,%1,%2,%3};"
        : "+f"(d[0]), "+f"(d[1]), "+f"(d[2]), "+f"(d[3])
        : "r"(a0), "r"(a1), "r"(a2), "r"(a3), "r"(b0), "r"(b1));
}
static __device__ __forceinline__ void cpa16(void* s, const void* g) {
    uint32_t sa = (uint32_t)__cvta_generic_to_shared(s);
    asm volatile("cp.async.ca.shared.global [%0], [%1], 16;" :: "r"(sa), "l"(g));
}
static __device__ __forceinline__ void cpa_commit() {
    asm volatile("cp.async.commit_group;");
}
static __device__ __forceinline__ void cpa_wait_all() {
    asm volatile("cp.async.wait_group 0;");
}

// ---------------------------------------------------------------------------
// Weight pre-conversion (tf32 round). W0 also re-laid-out to K-stride 56.
// ---------------------------------------------------------------------------
__global__ void __launch_bounds__(256) wconv0_k(const float* __restrict__ W0) {
    int idx = blockIdx.x * 256 + threadIdx.x;        // over 400*32*56
    if (idx >= 400 * 32 * 56) return;
    int k = idx % 56, row = idx / 56;                // row = loc*32+co
    g_W0c[idx] = (k < 54) ? tfround(W0[row * 54 + k]) : 0.0f;
}
__global__ void __launch_bounds__(256) wconv_k(const float* __restrict__ src,
                                               float* __restrict__ dst, int n) {
    int idx = blockIdx.x * 256 + threadIdx.x;
    if (idx < n) dst[idx] = tfround(src[idx]);
}

// ---------------------------------------------------------------------------
// im2col: x[B,6,60,60] -> g_P0[loc][k(56-stride)][B], tf32-rounded.
// Vectorized: block = (c,h) row x 128 batches. float4 LDG -> smem transpose
// (odd pitch 61) -> float4 STG (512B coalesced per w per warp-group).
// ---------------------------------------------------------------------------
__global__ void __launch_bounds__(256) im2col_k(const float* __restrict__ x) {
    const int ch = blockIdx.x;          // 0..359
    const int c = ch / 60, h = ch % 60;
    const int b0 = blockIdx.y * 128;
    __shared__ float s[128 * 61];       // [batch][w], pitch 61 (odd)

    // Read: 128 batch-rows x 15 float4 (fully coalesced, full sectors)
    const float* src = x + (size_t)b0 * 21600 + c * 3600 + h * 60;
    for (int e = threadIdx.x; e < 128 * 15; e += 256) {
        int bl = e / 15, w4 = e - bl * 15;
        float4 v = *(const float4*)(src + (size_t)bl * 21600 + w4 * 4);
        float* d = &s[bl * 61 + w4 * 4];
        d[0] = v.x; d[1] = v.y; d[2] = v.z; d[3] = v.w;
    }
    __syncthreads();

    // Write: for each w, 128 batches via STG.128 (32 threads x float4)
    const int i = h / 3, dh = h % 3;
    const size_t rowbase = ((size_t)(i * 20) * 56 + c * 9 + dh * 3) * 4096;
    for (int e = threadIdx.x; e < 60 * 32; e += 256) {
        int w = e >> 5, lane = e & 31;
        int j = w / 3, dw = w - j * 3;
        int bl = lane * 4;
        float4 v = make_float4(tfround(s[(bl + 0) * 61 + w]),
                               tfround(s[(bl + 1) * 61 + w]),
                               tfround(s[(bl + 2) * 61 + w]),
                               tfround(s[(bl + 3) * 61 + w]));
        size_t row = rowbase + ((size_t)j * 56 + dw) * 4096;
        *(float4*)&g_P0[row + b0 + bl] = v;
    }
}

// ---------------------------------------------------------------------------
// Locally-connected GEMM on tf32 tensor cores (mma.sync m16n8k8).
// 256 threads = 8 warps. CTA tile: BB batches x COUT_BLK couts.
// All operands pre-rounded -> inner loop is pure LDS + MMA (no CVT).
// ---------------------------------------------------------------------------
template <int CIN, int KH, int KW, int WIN, int WOUT, int COUT, int COUT_BLK,
          int KCHUNK, int BB, int KSPLIT, bool PARTIAL, long long KZSTRIDE,
          int KTOT, int STAGES, bool ROUND_OUT>
static __device__ __forceinline__ void lc_mma_body(const float* __restrict__ in,
                                                   const float* __restrict__ W,
                                                   const float* __restrict__ bias,
                                                   float* __restrict__ out) {
    constexpr int KPER   = KTOT / KSPLIT;
    constexpr int NCHUNK = KPER / KCHUNK;
    constexpr int AS     = BB + 8;           // A smem stride (== 8 mod 32)
    constexpr int WS     = KCHUNK + 4;       // W smem stride (== 4 mod 8)
    constexpr int NCOT   = COUT_BLK / 16;    // cout tiles
    constexpr int B      = 4096;

    extern __shared__ __align__(16) float dsm[];
    float* Asm = dsm;                            // [STAGES][KCHUNK][AS]
    float* Wsm = dsm + STAGES * KCHUNK * AS;     // [STAGES][COUT_BLK][WS]

    const int loc = blockIdx.x;
    const int i = loc / WOUT, j = loc - i * WOUT;
    const int b0 = blockIdx.y * BB;
    const int cz = (blockIdx.z / KSPLIT) * COUT_BLK;
    const int kz = blockIdx.z % KSPLIT;
    const int t = threadIdx.x;
    const int lane = t & 31;
    const int wid = t >> 5;
    const int qr = lane >> 2, qc = lane & 3;
    const int cot = wid % NCOT;         // cout tile of this warp
    const int bg  = wid / NCOT;         // 64-batch group of this warp

    const float* Wl = W + ((size_t)loc * COUT + cz) * KTOT;
    float* ob = out + (size_t)kz * KZSTRIDE;
    const int kbeg = kz * KPER;

    auto load_stage = [&](int st, int k0) {
        float* As = Asm + st * KCHUNK * AS;
        float* Ws = Wsm + st * COUT_BLK * WS;
        for (int id = t; id < KCHUNK * BB / 4; id += 256) {
            int kc = id / (BB / 4), off = (id % (BB / 4)) * 4;
            int k = k0 + kc;
            int c = k / (KH * KW);
            int r = k - c * (KH * KW);
            int dh = r / KW, dw = r - dh * KW;
            int loc_in = (KH * i + dh) * WIN + KW * j + dw;
            cpa16(&As[kc * AS + off],
                  in + ((size_t)loc_in * CIN + c) * B + b0 + off);
        }
        for (int id = t; id < COUT_BLK * KCHUNK / 4; id += 256) {
            int co = id / (KCHUNK / 4), off = (id % (KCHUNK / 4)) * 4;
            cpa16(&Ws[co * WS + off], Wl + (size_t)co * KTOT + k0 + off);
        }
        cpa_commit();
    };

    float acc[8][4];
#pragma unroll
    for (int nt = 0; nt < 8; nt++)
#pragma unroll
        for (int r = 0; r < 4; r++) acc[nt][r] = 0.0f;

    load_stage(0, kbeg);
    for (int ch = 0; ch < NCHUNK; ch++) {
        cpa_wait_all();
        __syncthreads();
        if (STAGES == 2 && ch + 1 < NCHUNK)
            load_stage((ch + 1) & 1, kbeg + (ch + 1) * KCHUNK);

        const int st = (STAGES == 2) ? (ch & 1) : 0;
        const float* As = Asm + st * KCHUNK * AS;
        const float* Ws = Wsm + st * COUT_BLK * WS;

#pragma unroll
        for (int kk = 0; kk < KCHUNK; kk += 8) {
            const float* wrow = Ws + (cot * 16 + qr) * WS + kk + qc;
            uint32_t a0 = __float_as_uint(wrow[0]);
            uint32_t a1 = __float_as_uint(wrow[8 * WS]);
            uint32_t a2 = __float_as_uint(wrow[4]);
            uint32_t a3 = __float_as_uint(wrow[8 * WS + 4]);
            const float* ar0 = As + (kk + qc) * AS + bg * 64;
            const float* ar1 = ar0 + 4 * AS;
#pragma unroll
            for (int p = 0; p < 4; p++) {
                float2 v0 = *(const float2*)(ar0 + p * 16 + 2 * qr);
                float2 v1 = *(const float2*)(ar1 + p * 16 + 2 * qr);
                mma_tf32(acc[p * 2 + 0], a0, a1, a2, a3,
                         __float_as_uint(v0.x), __float_as_uint(v1.x));
                mma_tf32(acc[p * 2 + 1], a0, a1, a2, a3,
                         __float_as_uint(v0.y), __float_as_uint(v1.y));
            }
        }
        if (STAGES == 1) break;
    }

    // Epilogue: stage to smem (reuse A buffer), then coalesced global writes.
    __syncthreads();
    constexpr int DS = BB + 8;
    float* Dsm = dsm;
#pragma unroll
    for (int p = 0; p < 4; p++) {
        int base = bg * 64 + p * 16 + 4 * qc;
        int row0 = cot * 16 + qr;
        *(float4*)&Dsm[row0 * DS + base] =
            make_float4(acc[2 * p][0], acc[2 * p + 1][0], acc[2 * p][1], acc[2 * p + 1][1]);
        *(float4*)&Dsm[(row0 + 8) * DS + base] =
            make_float4(acc[2 * p][2], acc[2 * p + 1][2], acc[2 * p][3], acc[2 * p + 1][3]);
    }
    __syncthreads();

    for (int idx = t; idx < COUT_BLK * BB; idx += 256) {
        int co = idx / BB, bl = idx - co * BB;
        float v = Dsm[co * DS + bl];
        if (!PARTIAL) {
            v = tanhap(v + bias[(size_t)loc * COUT + cz + co]);
            if (ROUND_OUT) v = tfround(v);
        }
        ob[((size_t)loc * COUT + cz + co) * B + b0 + bl] = v;
    }
}

// L0: K=56 (padded), single chunk. BB=256, COUT_BLK=32. Output tf32-rounded.
__global__ void __launch_bounds__(256) k_l0(const float* __restrict__ W,
                                            const float* __restrict__ b) {
    lc_mma_body<56, 1, 1, 20, 20, 32, 32, 56, 256, 1, false, 0, 56, 1, true>(
        g_P0, W, b, g_H0);
}
// L1: K=128, KCHUNK=32, 4 chunks, 2-stage. BB=128, COUT_BLK=64. Output tf32.
__global__ void __launch_bounds__(256) k_l1(const float* __restrict__ W,
                                            const float* __restrict__ b) {
    lc_mma_body<32, 2, 2, 20, 10, 64, 64, 32, 128, 1, false, 0, 128, 2, true>(
        g_H0, W, b, g_H1);
}
// L2: K=1600, split-K=4 (KPER=400), KCHUNK=40, 10 chunks, 2-stage. Partials.
__global__ void __launch_bounds__(256) k_l2(const float* __restrict__ W,
                                            const float* __restrict__ b) {
    lc_mma_body<64, 5, 5, 10, 2, 128, 64, 40, 128, 4, true, 4LL * 128 * 4096,
                1600, 2, false>(g_H1, W, b, g_PART);
}

// Reduce 4 split-K partials + bias + tanh -> g_H2 (fp32, classifier input)
__global__ void __launch_bounds__(256) l2_combine_k(const float* __restrict__ B2) {
    constexpr int ST4 = 4 * 128 * 4096 / 4;
    int idx4 = blockIdx.x * 256 + threadIdx.x;
    int row = idx4 >> 10;                         // loc*128+co
    const float4* p = (const float4*)g_PART;
    float4 s = p[idx4];
#pragma unroll
    for (int z = 1; z < 4; z++) {
        float4 v = p[idx4 + z * ST4];
        s.x += v.x; s.y += v.y; s.z += v.z; s.w += v.w;
    }
    float bv = B2[row];
    ((float4*)g_H2)[idx4] = make_float4(tanhap(s.x + bv), tanhap(s.y + bv),
                                        tanhap(s.z + bv), tanhap(s.w + bv));
}

// ---------------------------------------------------------------------------
// Classifier + softmax. 128 blocks x 256 threads: 32 batches x 8 f-groups.
// ---------------------------------------------------------------------------
__global__ void __launch_bounds__(256) classifier_k(const float* __restrict__ info,
                                                    const float* __restrict__ Wc,
                                                    const float* __restrict__ bc,
                                                    float* __restrict__ out) {
    __shared__ float wsm[1030];
    __shared__ float red[8][32][2];
    for (int e = threadIdx.x; e < 1028; e += 256) wsm[e] = Wc[e];
    if (threadIdx.x < 2) wsm[1028 + threadIdx.x] = bc[threadIdx.x];
    __syncthreads();

    const int fg = threadIdx.x >> 5, lane = threadIdx.x & 31;
    const int b = blockIdx.x * 32 + lane;
    float l0 = 0.f, l1 = 0.f;
#pragma unroll 8
    for (int ff = 0; ff < 64; ff++) {
        int f = fg * 64 + ff;
        int row = (f & 3) * 128 + (f >> 2);
        float hv = g_H2[(size_t)row * 4096 + b];
        l0 += hv * wsm[f * 2];
        l1 += hv * wsm[f * 2 + 1];
    }
    red[fg][lane][0] = l0;
    red[fg][lane][1] = l1;
    __syncthreads();

    if (threadIdx.x < 32) {
        int bb = blockIdx.x * 32 + threadIdx.x;
        float s0 = wsm[1028], s1 = wsm[1029];
#pragma unroll
        for (int g = 0; g < 8; g++) { s0 += red[g][threadIdx.x][0]; s1 += red[g][threadIdx.x][1]; }
        float i0 = info[2 * bb], i1 = info[2 * bb + 1];
        s0 += i0 * wsm[512 * 2]     + i1 * wsm[513 * 2];
        s1 += i0 * wsm[512 * 2 + 1] + i1 * wsm[513 * 2 + 1];
        float m = fmaxf(s0, s1);
        float e0 = __expf(s0 - m), e1 = __expf(s1 - m);
        float inv = 1.0f / (e0 + e1);
        ((float2*)out)[bb] = make_float2(e0 * inv, e1 * inv);
    }
}

extern "C" void kernel_launch(void* const* d_in, const int* in_sizes, int n_in,
                              void* d_out, int out_size) {
    const float* x    = (const float*)d_in[0];
    const float* info = (const float*)d_in[1];
    const float* W0   = (const float*)d_in[2];
    const float* B0   = (const float*)d_in[3];
    const float* W1   = (const float*)d_in[4];
    const float* B1   = (const float*)d_in[5];
    const float* W2   = (const float*)d_in[6];
    const float* B2   = (const float*)d_in[7];
    const float* Wc   = (const float*)d_in[8];
    const float* bc   = (const float*)d_in[9];
    float* out = (float*)d_out;

    // Dynamic smem: STAGES*(KCHUNK*AS + COUT_BLK*WS) floats
    const int s_l0 = (56 * 264 + 32 * 60) * 4;              // 66816
    const int s_l1 = 2 * (32 * 136 + 64 * 36) * 4;          // 53248
    const int s_l2 = 2 * (40 * 136 + 64 * 44) * 4;          // 66048
    cudaFuncSetAttribute(k_l0, cudaFuncAttributeMaxDynamicSharedMemorySize, s_l0);
    cudaFuncSetAttribute(k_l1, cudaFuncAttributeMaxDynamicSharedMemorySize, s_l1);
    cudaFuncSetAttribute(k_l2, cudaFuncAttributeMaxDynamicSharedMemorySize, s_l2);

    // Resolve device-symbol scratch to REAL device pointers.
    float* W0c; cudaGetSymbolAddress((void**)&W0c, g_W0c);
    float* W1c; cudaGetSymbolAddress((void**)&W1c, g_W1c);
    float* W2c; cudaGetSymbolAddress((void**)&W2c, g_W2c);

    wconv0_k<<<(400 * 32 * 56 + 255) / 256, 256>>>(W0);
    wconv_k<<<(100 * 64 * 128 + 255) / 256, 256>>>(W1, W1c, 100 * 64 * 128);
    wconv_k<<<(4 * 128 * 1600 + 255) / 256, 256>>>(W2, W2c, 4 * 128 * 1600);
    im2col_k<<<dim3(360, 32), 256>>>(x);
    k_l0<<<dim3(400, 16, 1), 256, s_l0>>>(W0c, B0);   // 6400 CTAs
    k_l1<<<dim3(100, 32, 1), 256, s_l1>>>(W1c, B1);   // 3200 CTAs
    k_l2<<<dim3(4, 32, 8), 256, s_l2>>>(W2c, B2);     // 1024 CTAs
    l2_combine_k<<<4 * 128 * 4096 / 4 / 256, 256>>>(B2);
    classifier_k<<<128, 256>>>(info, Wc, bc, out);
}

// round 11
// speedup vs baseline: 2.3686x; 1.3717x over previous
#include <cuda_runtime.h>
#include <cuda_bf16.h>
#include <cstdint>

// Activations/weights stored as bf16x2 k-pair words [loc][kp][batch] (batch innermost).
// Zero-init (bss) of unwritten pad rows is guaranteed; pad weights are explicit zeros.
__device__ uint32_t g_P0[400 * 32 * 4096];    // im2col, K'=64 padded (kp=32)
__device__ uint32_t g_H0[400 * 16 * 4096];    // l0 out, 32 couts -> 16 pairs
__device__ uint32_t g_H1[100 * 32 * 4096];    // l1 out, 64 couts -> 32 pairs
__device__ float    g_PART[4 * 4 * 128 * 4096]; // l2 split-K partials (fp32)
__device__ uint32_t g_W0c[400 * 32 * 32];     // [loc][co][kp], permuted + padded
__device__ uint32_t g_W1c[100 * 64 * 64];
__device__ uint32_t g_W2c[4 * 128 * 800];

static __device__ __forceinline__ float tanhap(float x) {
    float y; asm("tanh.approx.f32 %0, %1;" : "=f"(y) : "f"(x)); return y;
}
static __device__ __forceinline__ uint32_t packbf(float lo, float hi) {
    uint32_t r; asm("cvt.rn.bf16x2.f32 %0, %1, %2;" : "=r"(r) : "f"(hi), "f"(lo)); return r;
}
static __device__ __forceinline__ void mma_bf16(float* d, uint32_t a0, uint32_t a1,
                                                uint32_t a2, uint32_t a3,
                                                uint32_t b0, uint32_t b1) {
    asm volatile(
        "mma.sync.aligned.m16n8k16.row.col.f32.bf16.bf16.f32 "
        "{%0,%1,%2,%3}, {%4,%5,%6,%7}, {%8,%9}, {%0,%1,%2,%3};"
        : "+f"(d[0]), "+f"(d[1]), "+f"(d[2]), "+f"(d[3])
        : "r"(a0), "r"(a1), "r"(a2), "r"(a3), "r"(b0), "r"(b1));
}
static __device__ __forceinline__ void cpa16(void* s, const void* g) {
    uint32_t sa = (uint32_t)__cvta_generic_to_shared(s);
    asm volatile("cp.async.ca.shared.global [%0], [%1], 16;" :: "r"(sa), "l"(g));
}
static __device__ __forceinline__ void cpa_commit() {
    asm volatile("cp.async.commit_group;");
}
static __device__ __forceinline__ void cpa_wait_all() {
    asm volatile("cp.async.wait_group 0;");
}

// ---------------------------------------------------------------------------
// Weight pre-conversion to bf16x2 pair-packed, layer-specific k' permutation.
// L0: k' = c*10 + (dh*3+dw), slots q=9 and kp>=30 are zero pad. kp = c*5+m.
// ---------------------------------------------------------------------------
__global__ void __launch_bounds__(256) wconv0_k(const float* __restrict__ W0) {
    int idx = blockIdx.x * 256 + threadIdx.x;        // over 400*32*32
    if (idx >= 400 * 32 * 32) return;
    int kp = idx & 31, row = idx >> 5;               // row = loc*32+co
    uint32_t w = 0;
    if (kp < 30) {
        int c = kp / 5, m = kp - c * 5;
        int q0 = 2 * m, q1 = 2 * m + 1;
        float f0 = W0[row * 54 + c * 9 + q0];
        float f1 = (q1 < 9) ? W0[row * 54 + c * 9 + q1] : 0.0f;
        w = packbf(f0, f1);
    }
    g_W0c[idx] = w;
}
// L1: k' = r*32 + cin (r = dh*2+dw). kp = r*16 + cp.
__global__ void __launch_bounds__(256) wconv1_k(const float* __restrict__ W1) {
    int idx = blockIdx.x * 256 + threadIdx.x;        // over 100*64*64
    if (idx >= 100 * 64 * 64) return;
    int kp = idx & 63, row = idx >> 6;               // row = loc*64+co
    int r = kp >> 4, cp = kp & 15;
    const float* base = W1 + (size_t)row * 128;
    g_W1c[idx] = packbf(base[(2 * cp) * 4 + r], base[(2 * cp + 1) * 4 + r]);
}
// L2: k' = r*64 + cin (r = dh*5+dw). kp = r*32 + cp.
__global__ void __launch_bounds__(256) wconv2_k(const float* __restrict__ W2) {
    int idx = blockIdx.x * 256 + threadIdx.x;        // over 4*128*800
    if (idx >= 4 * 128 * 800) return;
    int kp = idx % 800, row = idx / 800;             // row = loc*128+co
    int r = kp >> 5, cp = kp & 31;
    const float* base = W2 + (size_t)row * 1600;
    g_W2c[idx] = packbf(base[(2 * cp) * 25 + r], base[(2 * cp + 1) * 25 + r]);
}

// ---------------------------------------------------------------------------
// im2col: x[B,6,60,60] -> g_P0[loc][kp][B] bf16x2 pair-packed.
// Block = (c, i) x 64 batches: loads 3 h-rows fully (all k-pairs block-local).
// kp = c*5 + m; word m = {q=2m, q=2m+1} with q = dh*3+dw (m=4 pairs with pad).
// ---------------------------------------------------------------------------
__global__ void __launch_bounds__(256) im2col_k(const float* __restrict__ x) {
    const int ci = blockIdx.x;          // 0..119
    const int c = ci / 20, i = ci % 20;
    const int b0 = blockIdx.y * 64;
    constexpr int P = 65;
    __shared__ float s[3 * 60 * P];     // [dh*60 + w][bl]

    // Read: 3 rows x 64 batches x 15 float4, coalesced; scalar scatter (~2-way)
    const float* src = x + c * 3600 + (3 * i) * 60;
    for (int e = threadIdx.x; e < 3 * 64 * 15; e += 256) {
        int dh = e / 960, rem = e - dh * 960;
        int bl = rem / 15, w4 = rem - bl * 15;
        float4 v = *(const float4*)(src + (size_t)(b0 + bl) * 21600 + dh * 60 + 4 * w4);
        float* d = &s[(dh * 60 + 4 * w4) * P + bl];
        d[0] = v.x; d[P] = v.y; d[2 * P] = v.z; d[3 * P] = v.w;
    }
    __syncthreads();

    // Write: per (j, m, bl4): gather pair values (conflict-free), pack, STG.128
    for (int e = threadIdx.x; e < 20 * 5 * 16; e += 256) {
        int bl4 = e & 15, jm = e >> 4;
        int j = jm / 5, m = jm - j * 5;
        int q0 = 2 * m;
        int dh0 = q0 / 3, dw0 = q0 - 3 * dh0;
        bool has1 = (m < 4);
        int q1 = q0 + 1;
        int dh1 = q1 / 3, dw1 = q1 - 3 * dh1;
        const float* s0 = &s[(dh0 * 60 + 3 * j + dw0) * P + 4 * bl4];
        const float* s1 = &s[(dh1 * 60 + 3 * j + dw1) * P + 4 * bl4];
        uint32_t w[4];
#pragma unroll
        for (int t = 0; t < 4; t++)
            w[t] = packbf(s0[t], has1 ? s1[t] : 0.0f);
        *(uint4*)&g_P0[((size_t)(i * 20 + j) * 32 + c * 5 + m) * 4096 + b0 + 4 * bl4] =
            make_uint4(w[0], w[1], w[2], w[3]);
    }
}

// ---------------------------------------------------------------------------
// Locally-connected GEMM on bf16 tensor cores (mma.sync m16n8k16).
// 256 threads = 8 warps. CTA tile: BB batches x COUT_BLK couts.
// smem elems are bf16x2 k-pair words; inner loop = pure LDS + MMA.
// MODE: A-row mapping (0: l0 direct, 1: l1, 2: l2). KTOT/KCHUNK in kp units.
// ---------------------------------------------------------------------------
template <int MODE, int WOUT, int COUT, int COUT_BLK, int KCHUNK, int BB,
          int KSPLIT, bool PARTIAL, long long KZSTRIDE, int KTOT, int STAGES>
static __device__ __forceinline__ void lc_mma_body(const uint32_t* __restrict__ in,
                                                   const uint32_t* __restrict__ W,
                                                   const float* __restrict__ bias,
                                                   void* __restrict__ outp) {
    constexpr int KPER   = KTOT / KSPLIT;
    constexpr int NCHUNK = KPER / KCHUNK;
    constexpr int AS     = BB + 8;           // A smem stride (words, == 8 mod 32)
    constexpr int WS     = KCHUNK + 4;       // W smem stride
    constexpr int NCOT   = COUT_BLK / 16;
    constexpr int B      = 4096;

    extern __shared__ __align__(16) uint32_t dsm[];
    uint32_t* Asm = dsm;                         // [STAGES][KCHUNK][AS]
    uint32_t* Wsm = dsm + STAGES * KCHUNK * AS;  // [STAGES][COUT_BLK][WS]

    const int loc = blockIdx.x;
    const int i = loc / WOUT, j = loc - i * WOUT;
    const int b0 = blockIdx.y * BB;
    const int cz = (blockIdx.z / KSPLIT) * COUT_BLK;
    const int kz = blockIdx.z % KSPLIT;
    const int t = threadIdx.x;
    const int lane = t & 31;
    const int wid = t >> 5;
    const int qr = lane >> 2, qc = lane & 3;
    const int cot = wid % NCOT;
    const int bg  = wid / NCOT;

    const uint32_t* Wl = W + ((size_t)loc * COUT + cz) * KTOT;
    const int kbeg = kz * KPER;

    auto load_stage = [&](int st, int kp0) {
        uint32_t* As = Asm + st * KCHUNK * AS;
        uint32_t* Ws = Wsm + st * COUT_BLK * WS;
        for (int id = t; id < KCHUNK * BB / 4; id += 256) {
            int kc = id / (BB / 4), off = (id % (BB / 4)) * 4;
            int kp = kp0 + kc;
            int row;
            if (MODE == 0) {
                row = loc * 32 + kp;
            } else if (MODE == 1) {
                int r = kp >> 4, cp = kp & 15;
                int loc_in = (2 * i + (r >> 1)) * 20 + 2 * j + (r & 1);
                row = loc_in * 16 + cp;
            } else {
                int r = kp >> 5, cp = kp & 31;
                int dh = r / 5, dw = r - 5 * dh;
                int loc_in = (5 * i + dh) * 10 + 5 * j + dw;
                row = loc_in * 32 + cp;
            }
            cpa16(&As[kc * AS + off], in + (size_t)row * B + b0 + off);
        }
        for (int id = t; id < COUT_BLK * KCHUNK / 4; id += 256) {
            int co = id / (KCHUNK / 4), off = (id % (KCHUNK / 4)) * 4;
            cpa16(&Ws[co * WS + off], Wl + (size_t)co * KTOT + kp0 + off);
        }
        cpa_commit();
    };

    float acc[8][4];
#pragma unroll
    for (int nt = 0; nt < 8; nt++)
#pragma unroll
        for (int r = 0; r < 4; r++) acc[nt][r] = 0.0f;

    load_stage(0, kbeg);
    for (int ch = 0; ch < NCHUNK; ch++) {
        cpa_wait_all();
        __syncthreads();
        if (STAGES == 2 && ch + 1 < NCHUNK)
            load_stage((ch + 1) & 1, kbeg + (ch + 1) * KCHUNK);

        const int st = (STAGES == 2) ? (ch & 1) : 0;
        const uint32_t* As = Asm + st * KCHUNK * AS;
        const uint32_t* Ws = Wsm + st * COUT_BLK * WS;

#pragma unroll
        for (int kk = 0; kk < KCHUNK; kk += 8) {   // 8 kp words = k16 step
            uint32_t a0 = Ws[(cot * 16 + qr) * WS + kk + qc];
            uint32_t a1 = Ws[(cot * 16 + qr + 8) * WS + kk + qc];
            uint32_t a2 = Ws[(cot * 16 + qr) * WS + kk + qc + 4];
            uint32_t a3 = Ws[(cot * 16 + qr + 8) * WS + kk + qc + 4];
#pragma unroll
            for (int p = 0; p < 4; p++) {
                int ab = bg * 64 + p * 16 + 2 * qr;
                uint2 v0 = *(const uint2*)&As[(kk + qc) * AS + ab];
                uint2 v1 = *(const uint2*)&As[(kk + qc + 4) * AS + ab];
                mma_bf16(acc[p * 2 + 0], a0, a1, a2, a3, v0.x, v1.x);
                mma_bf16(acc[p * 2 + 1], a0, a1, a2, a3, v0.y, v1.y);
            }
        }
        if (STAGES == 1) break;
    }

    // Epilogue: stage fp32 D to smem, then coalesced global writes.
    __syncthreads();
    constexpr int DS = BB + 8;
    float* Dsm = (float*)dsm;
#pragma unroll
    for (int p = 0; p < 4; p++) {
        int base = bg * 64 + p * 16 + 4 * qc;
        int row0 = cot * 16 + qr;
        *(float4*)&Dsm[row0 * DS + base] =
            make_float4(acc[2 * p][0], acc[2 * p + 1][0], acc[2 * p][1], acc[2 * p + 1][1]);
        *(float4*)&Dsm[(row0 + 8) * DS + base] =
            make_float4(acc[2 * p][2], acc[2 * p + 1][2], acc[2 * p][3], acc[2 * p + 1][3]);
    }
    __syncthreads();

    if (PARTIAL) {
        float* ob = (float*)outp + (size_t)kz * KZSTRIDE;
        for (int idx = t; idx < COUT_BLK * BB; idx += 256) {
            int co = idx / BB, bl = idx - co * BB;
            ob[((size_t)loc * COUT + cz + co) * B + b0 + bl] = Dsm[co * DS + bl];
        }
    } else {
        uint32_t* ob = (uint32_t*)outp;
        for (int idx = t; idx < (COUT_BLK / 2) * BB; idx += 256) {
            int cop = idx / BB, bl = idx - cop * BB;
            float d0 = tanhap(Dsm[(2 * cop) * DS + bl] +
                              bias[(size_t)loc * COUT + cz + 2 * cop]);
            float d1 = tanhap(Dsm[(2 * cop + 1) * DS + bl] +
                              bias[(size_t)loc * COUT + cz + 2 * cop + 1]);
            ob[((size_t)loc * (COUT / 2) + (cz >> 1) + cop) * B + b0 + bl] =
                packbf(d0, d1);
        }
    }
}

// L0: KTOT=32 kp (K'=64 padded), 1 chunk, BB=256, COUT_BLK=32.
__global__ void __launch_bounds__(256) k_l0(const float* __restrict__ b) {
    lc_mma_body<0, 20, 32, 32, 32, 256, 1, false, 0, 32, 1>(g_P0, g_W0c, b, g_H0);
}
// L1: KTOT=64 kp, KCHUNK=32, 2 chunks, 2-stage, BB=128, COUT_BLK=64.
__global__ void __launch_bounds__(256) k_l1(const float* __restrict__ b) {
    lc_mma_body<1, 10, 64, 64, 32, 128, 1, false, 0, 64, 2>(g_H0, g_W1c, b, g_H1);
}
// L2: KTOT=800 kp, split-K=4 (200 kp), KCHUNK=40, 5 chunks, 2-stage. Partials.
__global__ void __launch_bounds__(256) k_l2(const float* __restrict__ b) {
    lc_mma_body<2, 2, 128, 64, 40, 128, 4, true, 4LL * 128 * 4096, 800, 2>(
        g_H1, g_W2c, b, g_PART);
}

// ---------------------------------------------------------------------------
// Classifier + softmax with l2 split-K combine FUSED (bias + tanh inline).
// 128 blocks x 256 threads: 32 batches x 8 f-groups.
// flatten f = c*4 + loc2; partial row = loc2*128 + c = (f&3)*128 + (f>>2).
// ---------------------------------------------------------------------------
__global__ void __launch_bounds__(256) classifier_k(const float* __restrict__ info,
                                                    const float* __restrict__ Wc,
                                                    const float* __restrict__ bc,
                                                    const float* __restrict__ B2,
                                                    float* __restrict__ out) {
    constexpr int ST = 4 * 128 * 4096;
    __shared__ float wsm[1030];
    __shared__ float bsm[512];
    __shared__ float red[8][32][2];
    for (int e = threadIdx.x; e < 1028; e += 256) wsm[e] = Wc[e];
    if (threadIdx.x < 2) wsm[1028 + threadIdx.x] = bc[threadIdx.x];
    for (int e = threadIdx.x; e < 512; e += 256) bsm[e] = B2[e];
    __syncthreads();

    const int fg = threadIdx.x >> 5, lane = threadIdx.x & 31;
    const int b = blockIdx.x * 32 + lane;
    float l0 = 0.f, l1 = 0.f;
#pragma unroll 4
    for (int ff = 0; ff < 64; ff++) {
        int f = fg * 64 + ff;
        int row = (f & 3) * 128 + (f >> 2);
        size_t base = (size_t)row * 4096 + b;
        float s = bsm[row] + g_PART[base] + g_PART[base + ST]
                + g_PART[base + 2 * ST] + g_PART[base + 3 * ST];
        float hv = tanhap(s);
        l0 += hv * wsm[f * 2];
        l1 += hv * wsm[f * 2 + 1];
    }
    red[fg][lane][0] = l0;
    red[fg][lane][1] = l1;
    __syncthreads();

    if (threadIdx.x < 32) {
        int bb = blockIdx.x * 32 + threadIdx.x;
        float s0 = wsm[1028], s1 = wsm[1029];
#pragma unroll
        for (int g = 0; g < 8; g++) { s0 += red[g][threadIdx.x][0]; s1 += red[g][threadIdx.x][1]; }
        float i0 = info[2 * bb], i1 = info[2 * bb + 1];
        s0 += i0 * wsm[512 * 2]     + i1 * wsm[513 * 2];
        s1 += i0 * wsm[512 * 2 + 1] + i1 * wsm[513 * 2 + 1];
        float m = fmaxf(s0, s1);
        float e0 = __expf(s0 - m), e1 = __expf(s1 - m);
        float inv = 1.0f / (e0 + e1);
        ((float2*)out)[bb] = make_float2(e0 * inv, e1 * inv);
    }
}

extern "C" void kernel_launch(void* const* d_in, const int* in_sizes, int n_in,
                              void* d_out, int out_size) {
    const float* x    = (const float*)d_in[0];
    const float* info = (const float*)d_in[1];
    const float* W0   = (const float*)d_in[2];
    const float* B0   = (const float*)d_in[3];
    const float* W1   = (const float*)d_in[4];
    const float* B1   = (const float*)d_in[5];
    const float* W2   = (const float*)d_in[6];
    const float* B2   = (const float*)d_in[7];
    const float* Wc   = (const float*)d_in[8];
    const float* bc   = (const float*)d_in[9];
    float* out = (float*)d_out;

    // Dynamic smem: STAGES*(KCHUNK*AS + COUT_BLK*WS) words (4B each)
    const int s_l0 = (32 * 264 + 32 * 36) * 4;              // 38400
    const int s_l1 = 2 * (32 * 136 + 64 * 36) * 4;          // 53248
    const int s_l2 = 2 * (40 * 136 + 64 * 44) * 4;          // 66048
    cudaFuncSetAttribute(k_l0, cudaFuncAttributeMaxDynamicSharedMemorySize, s_l0);
    cudaFuncSetAttribute(k_l1, cudaFuncAttributeMaxDynamicSharedMemorySize, s_l1);
    cudaFuncSetAttribute(k_l2, cudaFuncAttributeMaxDynamicSharedMemorySize, s_l2);

    wconv0_k<<<(400 * 32 * 32 + 255) / 256, 256>>>(W0);
    wconv1_k<<<(100 * 64 * 64 + 255) / 256, 256>>>(W1);
    wconv2_k<<<(4 * 128 * 800 + 255) / 256, 256>>>(W2);
    im2col_k<<<dim3(120, 64), 256>>>(x);
    k_l0<<<dim3(400, 16, 1), 256, s_l0>>>(B0);        // 6400 CTAs
    k_l1<<<dim3(100, 32, 1), 256, s_l1>>>(B1);        // 3200 CTAs
    k_l2<<<dim3(4, 32, 8), 256, s_l2>>>(B2);          // 1024 CTAs (2 co x 4 kz)
    classifier_k<<<128, 256>>>(info, Wc, bc, B2, out);
}

// round 12
// speedup vs baseline: 2.3860x; 1.0073x over previous
#include <cuda_runtime.h>
#include <cuda_bf16.h>
#include <cstdint>

// Activations/weights stored as bf16x2 k-pair words [loc][kp][batch] (batch innermost).
// Zero-init (bss) of unwritten pad rows is guaranteed; pad weights are explicit zeros.
__device__ uint32_t g_P0[400 * 32 * 4096];    // im2col, K'=64 padded (kp=32)
__device__ uint32_t g_H0[400 * 16 * 4096];    // l0 out, 32 couts -> 16 pairs
__device__ uint32_t g_H1[100 * 32 * 4096];    // l1 out, 64 couts -> 32 pairs
__device__ float    g_PART[4 * 4 * 128 * 4096]; // l2 split-K partials (fp32)
__device__ uint32_t g_W0c[400 * 32 * 32];     // [loc][co][kp], permuted + padded
__device__ uint32_t g_W1c[100 * 64 * 64];
__device__ uint32_t g_W2c[4 * 128 * 800];

static __device__ __forceinline__ float tanhap(float x) {
    float y; asm("tanh.approx.f32 %0, %1;" : "=f"(y) : "f"(x)); return y;
}
static __device__ __forceinline__ uint32_t packbf(float lo, float hi) {
    uint32_t r; asm("cvt.rn.bf16x2.f32 %0, %1, %2;" : "=r"(r) : "f"(hi), "f"(lo)); return r;
}
static __device__ __forceinline__ void mma_bf16(float* d, uint32_t a0, uint32_t a1,
                                                uint32_t a2, uint32_t a3,
                                                uint32_t b0, uint32_t b1) {
    asm volatile(
        "mma.sync.aligned.m16n8k16.row.col.f32.bf16.bf16.f32 "
        "{%0,%1,%2,%3}, {%4,%5,%6,%7}, {%8,%9}, {%0,%1,%2,%3};"
        : "+f"(d[0]), "+f"(d[1]), "+f"(d[2]), "+f"(d[3])
        : "r"(a0), "r"(a1), "r"(a2), "r"(a3), "r"(b0), "r"(b1));
}
static __device__ __forceinline__ void cpa16(void* s, const void* g) {
    uint32_t sa = (uint32_t)__cvta_generic_to_shared(s);
    asm volatile("cp.async.ca.shared.global [%0], [%1], 16;" :: "r"(sa), "l"(g));
}
static __device__ __forceinline__ void cpa_commit() {
    asm volatile("cp.async.commit_group;");
}
static __device__ __forceinline__ void cpa_wait_all() {
    asm volatile("cp.async.wait_group 0;");
}

// ---------------------------------------------------------------------------
// Weight pre-conversion to bf16x2 pair-packed, layer-specific k' permutation.
// L0: k' = c*10 + (dh*3+dw), slots q=9 and kp>=30 are zero pad. kp = c*5+m.
// ---------------------------------------------------------------------------
__global__ void __launch_bounds__(256) wconv0_k(const float* __restrict__ W0) {
    int idx = blockIdx.x * 256 + threadIdx.x;        // over 400*32*32
    if (idx >= 400 * 32 * 32) return;
    int kp = idx & 31, row = idx >> 5;               // row = loc*32+co
    uint32_t w = 0;
    if (kp < 30) {
        int c = kp / 5, m = kp - c * 5;
        int q0 = 2 * m, q1 = 2 * m + 1;
        float f0 = W0[row * 54 + c * 9 + q0];
        float f1 = (q1 < 9) ? W0[row * 54 + c * 9 + q1] : 0.0f;
        w = packbf(f0, f1);
    }
    g_W0c[idx] = w;
}
// L1: k' = r*32 + cin (r = dh*2+dw). kp = r*16 + cp.
__global__ void __launch_bounds__(256) wconv1_k(const float* __restrict__ W1) {
    int idx = blockIdx.x * 256 + threadIdx.x;        // over 100*64*64
    if (idx >= 100 * 64 * 64) return;
    int kp = idx & 63, row = idx >> 6;               // row = loc*64+co
    int r = kp >> 4, cp = kp & 15;
    const float* base = W1 + (size_t)row * 128;
    g_W1c[idx] = packbf(base[(2 * cp) * 4 + r], base[(2 * cp + 1) * 4 + r]);
}
// L2: k' = r*64 + cin (r = dh*5+dw). kp = r*32 + cp.
__global__ void __launch_bounds__(256) wconv2_k(const float* __restrict__ W2) {
    int idx = blockIdx.x * 256 + threadIdx.x;        // over 4*128*800
    if (idx >= 4 * 128 * 800) return;
    int kp = idx % 800, row = idx / 800;             // row = loc*128+co
    int r = kp >> 5, cp = kp & 31;
    const float* base = W2 + (size_t)row * 1600;
    g_W2c[idx] = packbf(base[(2 * cp) * 25 + r], base[(2 * cp + 1) * 25 + r]);
}

// ---------------------------------------------------------------------------
// im2col: x[B,6,60,60] -> g_P0[loc][kp][B] bf16x2 pair-packed.
// Block = (c, i) x 64 batches: loads 3 h-rows fully (all k-pairs block-local).
// kp = c*5 + m; word m = {q=2m, q=2m+1} with q = dh*3+dw (m=4 pairs with pad).
// ---------------------------------------------------------------------------
__global__ void __launch_bounds__(256) im2col_k(const float* __restrict__ x) {
    const int ci = blockIdx.x;          // 0..119
    const int c = ci / 20, i = ci % 20;
    const int b0 = blockIdx.y * 64;
    constexpr int P = 65;
    __shared__ float s[3 * 60 * P];     // [dh*60 + w][bl]

    // Read: 3 rows x 64 batches x 15 float4, coalesced; scalar scatter (~2-way)
    const float* src = x + c * 3600 + (3 * i) * 60;
    for (int e = threadIdx.x; e < 3 * 64 * 15; e += 256) {
        int dh = e / 960, rem = e - dh * 960;
        int bl = rem / 15, w4 = rem - bl * 15;
        float4 v = *(const float4*)(src + (size_t)(b0 + bl) * 21600 + dh * 60 + 4 * w4);
        float* d = &s[(dh * 60 + 4 * w4) * P + bl];
        d[0] = v.x; d[P] = v.y; d[2 * P] = v.z; d[3 * P] = v.w;
    }
    __syncthreads();

    // Write: per (j, m, bl4): gather pair values (conflict-free), pack, STG.128
    for (int e = threadIdx.x; e < 20 * 5 * 16; e += 256) {
        int bl4 = e & 15, jm = e >> 4;
        int j = jm / 5, m = jm - j * 5;
        int q0 = 2 * m;
        int dh0 = q0 / 3, dw0 = q0 - 3 * dh0;
        bool has1 = (m < 4);
        int q1 = q0 + 1;
        int dh1 = q1 / 3, dw1 = q1 - 3 * dh1;
        const float* s0 = &s[(dh0 * 60 + 3 * j + dw0) * P + 4 * bl4];
        const float* s1 = &s[(dh1 * 60 + 3 * j + dw1) * P + 4 * bl4];
        uint32_t w[4];
#pragma unroll
        for (int t = 0; t < 4; t++)
            w[t] = packbf(s0[t], has1 ? s1[t] : 0.0f);
        *(uint4*)&g_P0[((size_t)(i * 20 + j) * 32 + c * 5 + m) * 4096 + b0 + 4 * bl4] =
            make_uint4(w[0], w[1], w[2], w[3]);
    }
}

// ---------------------------------------------------------------------------
// Locally-connected GEMM on bf16 tensor cores (mma.sync m16n8k16).
// 256 threads = 8 warps. CTA tile: BB batches x COUT_BLK couts.
// smem elems are bf16x2 k-pair words; inner loop = pure LDS + MMA.
// MODE: A-row mapping (0: l0 direct, 1: l1, 2: l2). KTOT/KCHUNK in kp units.
// ---------------------------------------------------------------------------
template <int MODE, int WOUT, int COUT, int COUT_BLK, int KCHUNK, int BB,
          int KSPLIT, bool PARTIAL, long long KZSTRIDE, int KTOT, int STAGES>
static __device__ __forceinline__ void lc_mma_body(const uint32_t* __restrict__ in,
                                                   const uint32_t* __restrict__ W,
                                                   const float* __restrict__ bias,
                                                   void* __restrict__ outp) {
    constexpr int KPER   = KTOT / KSPLIT;
    constexpr int NCHUNK = KPER / KCHUNK;
    constexpr int AS     = BB + 8;           // A smem stride (words, == 8 mod 32)
    constexpr int WS     = KCHUNK + 4;       // W smem stride
    constexpr int NCOT   = COUT_BLK / 16;
    constexpr int B      = 4096;

    extern __shared__ __align__(16) uint32_t dsm[];
    uint32_t* Asm = dsm;                         // [STAGES][KCHUNK][AS]
    uint32_t* Wsm = dsm + STAGES * KCHUNK * AS;  // [STAGES][COUT_BLK][WS]

    const int loc = blockIdx.x;
    const int i = loc / WOUT, j = loc - i * WOUT;
    const int b0 = blockIdx.y * BB;
    const int cz = (blockIdx.z / KSPLIT) * COUT_BLK;
    const int kz = blockIdx.z % KSPLIT;
    const int t = threadIdx.x;
    const int lane = t & 31;
    const int wid = t >> 5;
    const int qr = lane >> 2, qc = lane & 3;
    const int cot = wid % NCOT;
    const int bg  = wid / NCOT;

    const uint32_t* Wl = W + ((size_t)loc * COUT + cz) * KTOT;
    const int kbeg = kz * KPER;

    auto load_stage = [&](int st, int kp0) {
        uint32_t* As = Asm + st * KCHUNK * AS;
        uint32_t* Ws = Wsm + st * COUT_BLK * WS;
        for (int id = t; id < KCHUNK * BB / 4; id += 256) {
            int kc = id / (BB / 4), off = (id % (BB / 4)) * 4;
            int kp = kp0 + kc;
            int row;
            if (MODE == 0) {
                row = loc * 32 + kp;
            } else if (MODE == 1) {
                int r = kp >> 4, cp = kp & 15;
                int loc_in = (2 * i + (r >> 1)) * 20 + 2 * j + (r & 1);
                row = loc_in * 16 + cp;
            } else {
                int r = kp >> 5, cp = kp & 31;
                int dh = r / 5, dw = r - 5 * dh;
                int loc_in = (5 * i + dh) * 10 + 5 * j + dw;
                row = loc_in * 32 + cp;
            }
            cpa16(&As[kc * AS + off], in + (size_t)row * B + b0 + off);
        }
        for (int id = t; id < COUT_BLK * KCHUNK / 4; id += 256) {
            int co = id / (KCHUNK / 4), off = (id % (KCHUNK / 4)) * 4;
            cpa16(&Ws[co * WS + off], Wl + (size_t)co * KTOT + kp0 + off);
        }
        cpa_commit();
    };

    float acc[8][4];
#pragma unroll
    for (int nt = 0; nt < 8; nt++)
#pragma unroll
        for (int r = 0; r < 4; r++) acc[nt][r] = 0.0f;

    load_stage(0, kbeg);
    for (int ch = 0; ch < NCHUNK; ch++) {
        cpa_wait_all();
        __syncthreads();
        if (STAGES == 2 && ch + 1 < NCHUNK)
            load_stage((ch + 1) & 1, kbeg + (ch + 1) * KCHUNK);

        const int st = (STAGES == 2) ? (ch & 1) : 0;
        const uint32_t* As = Asm + st * KCHUNK * AS;
        const uint32_t* Ws = Wsm + st * COUT_BLK * WS;

#pragma unroll
        for (int kk = 0; kk < KCHUNK; kk += 8) {   // 8 kp words = k16 step
            uint32_t a0 = Ws[(cot * 16 + qr) * WS + kk + qc];
            uint32_t a1 = Ws[(cot * 16 + qr + 8) * WS + kk + qc];
            uint32_t a2 = Ws[(cot * 16 + qr) * WS + kk + qc + 4];
            uint32_t a3 = Ws[(cot * 16 + qr + 8) * WS + kk + qc + 4];
#pragma unroll
            for (int p = 0; p < 4; p++) {
                int ab = bg * 64 + p * 16 + 2 * qr;
                uint2 v0 = *(const uint2*)&As[(kk + qc) * AS + ab];
                uint2 v1 = *(const uint2*)&As[(kk + qc + 4) * AS + ab];
                mma_bf16(acc[p * 2 + 0], a0, a1, a2, a3, v0.x, v1.x);
                mma_bf16(acc[p * 2 + 1], a0, a1, a2, a3, v0.y, v1.y);
            }
        }
        if (STAGES == 1) break;
    }

    // Epilogue: stage fp32 D to smem, then coalesced global writes.
    __syncthreads();
    constexpr int DS = BB + 8;
    float* Dsm = (float*)dsm;
#pragma unroll
    for (int p = 0; p < 4; p++) {
        int base = bg * 64 + p * 16 + 4 * qc;
        int row0 = cot * 16 + qr;
        *(float4*)&Dsm[row0 * DS + base] =
            make_float4(acc[2 * p][0], acc[2 * p + 1][0], acc[2 * p][1], acc[2 * p + 1][1]);
        *(float4*)&Dsm[(row0 + 8) * DS + base] =
            make_float4(acc[2 * p][2], acc[2 * p + 1][2], acc[2 * p][3], acc[2 * p + 1][3]);
    }
    __syncthreads();

    if (PARTIAL) {
        float* ob = (float*)outp + (size_t)kz * KZSTRIDE;
        for (int idx = t; idx < COUT_BLK * BB; idx += 256) {
            int co = idx / BB, bl = idx - co * BB;
            ob[((size_t)loc * COUT + cz + co) * B + b0 + bl] = Dsm[co * DS + bl];
        }
    } else {
        uint32_t* ob = (uint32_t*)outp;
        for (int idx = t; idx < (COUT_BLK / 2) * BB; idx += 256) {
            int cop = idx / BB, bl = idx - cop * BB;
            float d0 = tanhap(Dsm[(2 * cop) * DS + bl] +
                              bias[(size_t)loc * COUT + cz + 2 * cop]);
            float d1 = tanhap(Dsm[(2 * cop + 1) * DS + bl] +
                              bias[(size_t)loc * COUT + cz + 2 * cop + 1]);
            ob[((size_t)loc * (COUT / 2) + (cz >> 1) + cop) * B + b0 + bl] =
                packbf(d0, d1);
        }
    }
}

// L0: KTOT=32 kp (K'=64 padded), 1 chunk, BB=256, COUT_BLK=32.
__global__ void __launch_bounds__(256) k_l0(const float* __restrict__ b) {
    lc_mma_body<0, 20, 32, 32, 32, 256, 1, false, 0, 32, 1>(g_P0, g_W0c, b, g_H0);
}
// L1: KTOT=64 kp, KCHUNK=32, 2 chunks, 2-stage, BB=128, COUT_BLK=64.
__global__ void __launch_bounds__(256) k_l1(const float* __restrict__ b) {
    lc_mma_body<1, 10, 64, 64, 32, 128, 1, false, 0, 64, 2>(g_H0, g_W1c, b, g_H1);
}
// L2: KTOT=800 kp, split-K=4 (200 kp), KCHUNK=40, 5 chunks, 2-stage. Partials.
__global__ void __launch_bounds__(256) k_l2(const float* __restrict__ b) {
    lc_mma_body<2, 2, 128, 64, 40, 128, 4, true, 4LL * 128 * 4096, 800, 2>(
        g_H1, g_W2c, b, g_PART);
}

// ---------------------------------------------------------------------------
// Classifier + softmax with l2 split-K combine FUSED (bias + tanh inline).
// 128 blocks x 256 threads: 32 batches x 8 f-groups.
// flatten f = c*4 + loc2; partial row = loc2*128 + c = (f&3)*128 + (f>>2).
// ---------------------------------------------------------------------------
__global__ void __launch_bounds__(256) classifier_k(const float* __restrict__ info,
                                                    const float* __restrict__ Wc,
                                                    const float* __restrict__ bc,
                                                    const float* __restrict__ B2,
                                                    float* __restrict__ out) {
    constexpr int ST = 4 * 128 * 4096;
    __shared__ float wsm[1030];
    __shared__ float bsm[512];
    __shared__ float red[8][32][2];
    for (int e = threadIdx.x; e < 1028; e += 256) wsm[e] = Wc[e];
    if (threadIdx.x < 2) wsm[1028 + threadIdx.x] = bc[threadIdx.x];
    for (int e = threadIdx.x; e < 512; e += 256) bsm[e] = B2[e];
    __syncthreads();

    const int fg = threadIdx.x >> 5, lane = threadIdx.x & 31;
    const int b = blockIdx.x * 32 + lane;
    float l0 = 0.f, l1 = 0.f;
#pragma unroll 4
    for (int ff = 0; ff < 64; ff++) {
        int f = fg * 64 + ff;
        int row = (f & 3) * 128 + (f >> 2);
        size_t base = (size_t)row * 4096 + b;
        float s = bsm[row] + g_PART[base] + g_PART[base + ST]
                + g_PART[base + 2 * ST] + g_PART[base + 3 * ST];
        float hv = tanhap(s);
        l0 += hv * wsm[f * 2];
        l1 += hv * wsm[f * 2 + 1];
    }
    red[fg][lane][0] = l0;
    red[fg][lane][1] = l1;
    __syncthreads();

    if (threadIdx.x < 32) {
        int bb = blockIdx.x * 32 + threadIdx.x;
        float s0 = wsm[1028], s1 = wsm[1029];
#pragma unroll
        for (int g = 0; g < 8; g++) { s0 += red[g][threadIdx.x][0]; s1 += red[g][threadIdx.x][1]; }
        float i0 = info[2 * bb], i1 = info[2 * bb + 1];
        s0 += i0 * wsm[512 * 2]     + i1 * wsm[513 * 2];
        s1 += i0 * wsm[512 * 2 + 1] + i1 * wsm[513 * 2 + 1];
        float m = fmaxf(s0, s1);
        float e0 = __expf(s0 - m), e1 = __expf(s1 - m);
        float inv = 1.0f / (e0 + e1);
        ((float2*)out)[bb] = make_float2(e0 * inv, e1 * inv);
    }
}

extern "C" void kernel_launch(void* const* d_in, const int* in_sizes, int n_in,
                              void* d_out, int out_size) {
    const float* x    = (const float*)d_in[0];
    const float* info = (const float*)d_in[1];
    const float* W0   = (const float*)d_in[2];
    const float* B0   = (const float*)d_in[3];
    const float* W1   = (const float*)d_in[4];
    const float* B1   = (const float*)d_in[5];
    const float* W2   = (const float*)d_in[6];
    const float* B2   = (const float*)d_in[7];
    const float* Wc   = (const float*)d_in[8];
    const float* bc   = (const float*)d_in[9];
    float* out = (float*)d_out;

    // Dynamic smem: STAGES*(KCHUNK*AS + COUT_BLK*WS) words (4B each)
    const int s_l0 = (32 * 264 + 32 * 36) * 4;              // 38400
    const int s_l1 = 2 * (32 * 136 + 64 * 36) * 4;          // 53248
    const int s_l2 = 2 * (40 * 136 + 64 * 44) * 4;          // 66048
    cudaFuncSetAttribute(k_l0, cudaFuncAttributeMaxDynamicSharedMemorySize, s_l0);
    cudaFuncSetAttribute(k_l1, cudaFuncAttributeMaxDynamicSharedMemorySize, s_l1);
    cudaFuncSetAttribute(k_l2, cudaFuncAttributeMaxDynamicSharedMemorySize, s_l2);

    wconv0_k<<<(400 * 32 * 32 + 255) / 256, 256>>>(W0);
    wconv1_k<<<(100 * 64 * 64 + 255) / 256, 256>>>(W1);
    wconv2_k<<<(4 * 128 * 800 + 255) / 256, 256>>>(W2);
    im2col_k<<<dim3(120, 64), 256>>>(x);
    k_l0<<<dim3(400, 16, 1), 256, s_l0>>>(B0);        // 6400 CTAs
    k_l1<<<dim3(100, 32, 1), 256, s_l1>>>(B1);        // 3200 CTAs
    k_l2<<<dim3(4, 32, 8), 256, s_l2>>>(B2);          // 1024 CTAs (2 co x 4 kz)
    classifier_k<<<128, 256>>>(info, Wc, bc, B2, out);
}